// round 11
// baseline (speedup 1.0000x reference)
#include <cuda_runtime.h>
#include <cuda_fp16.h>
#include <math.h>
#include <stdint.h>

// Problem constants
#define Bb 2
#define Ss 2048
#define Dd 1024
#define Hh 16
#define HDh 64
#define Mm (Bb*Ss)   // 4096

// Scratch (device globals), all fp16-packed uint32 unless noted
// B2 layout: superblocks (n8, k32) of 128 words; lane l owns l*4+{0..3} =
//   [b0(k16 even), b1(even), b0(k16 odd), b1(odd)]
__device__ uint32_t g_xA[Mm*Dd/2];     // x, A-frag
__device__ uint32_t g_xB[Mm*Dd/2];     // x, B2-frag (n=s)
__device__ uint32_t g_wqB[Dd*Dd/2];    // B2
__device__ uint32_t g_wkB[Dd*Dd/2];    // B2
__device__ uint32_t g_woB[Dd*Dd/2];    // B2
__device__ uint32_t g_wvA[Dd*Dd/2];    // wv, A-frag (for transposed V gemm)
__device__ uint32_t g_qp[Mm*Dd/2];     // Q per (b,h), A-frag
__device__ uint32_t g_kp[Mm*Dd/2];     // K per (b,h), B2 (n=s, k=d)
__device__ uint32_t g_vp[Mm*Dd/2];     // V per (b,h), B2 (k=s, n=d)
__device__ uint32_t g_op[Mm*Dd/2];     // attn out, global A-frag
__device__ float    g_cos[Ss*32];
__device__ float    g_sin[Ss*32];

// ======================================================================
// Helpers
// ======================================================================
__device__ __forceinline__ uint32_t smem_u32(const void* p) {
    uint32_t a;
    asm("{ .reg .u64 t; cvta.to.shared.u64 t, %1; cvt.u32.u64 %0, t; }"
        : "=r"(a) : "l"(p));
    return a;
}
__device__ __forceinline__ uint32_t pk(float a, float b) {
    __half2 h = __floats2half2_rn(a, b);
    return *reinterpret_cast<uint32_t*>(&h);
}
__device__ __forceinline__ void mma16(float* d, const uint32_t* a,
                                      uint32_t b0, uint32_t b1) {
    asm volatile(
        "mma.sync.aligned.m16n8k16.row.col.f32.f16.f16.f32 "
        "{%0,%1,%2,%3}, {%4,%5,%6,%7}, {%8,%9}, {%0,%1,%2,%3};"
        : "+f"(d[0]), "+f"(d[1]), "+f"(d[2]), "+f"(d[3])
        : "r"(a[0]), "r"(a[1]), "r"(a[2]), "r"(a[3]), "r"(b0), "r"(b1));
}
__device__ __forceinline__ void cp16(uint32_t dst, const void* src) {
    asm volatile("cp.async.cg.shared.global [%0], [%1], 16;"
                 :: "r"(dst), "l"(src) : "memory");
}
#define CP_COMMIT() asm volatile("cp.async.commit_group;" ::: "memory")
#define CP_WAIT0()  asm volatile("cp.async.wait_group 0;" ::: "memory")
#define CP_WAIT1()  asm volatile("cp.async.wait_group 1;" ::: "memory")
#define CP_WAIT2()  asm volatile("cp.async.wait_group 2;" ::: "memory")

// ======================================================================
// RoPE cos/sin tables
// ======================================================================
__global__ void build_tab(float* __restrict__ ct, float* __restrict__ st)
{
    int idx = blockIdx.x * blockDim.x + threadIdx.x;
    int s = idx >> 5, i = idx & 31;
    double inv = pow(10000.0, -((double)(2 * i)) / (double)HDh);
    double sd, cd;
    sincos((double)s * inv, &sd, &cd);
    ct[idx] = (float)cd;
    st[idx] = (float)sd;
}

// ======================================================================
// permX: x -> xA (A-frag) AND xB (B2-frag) in one pass.
// ======================================================================
__global__ __launch_bounds__(256) void permX(const float* __restrict__ A)
{
    __shared__ float ts[64][68];
    const int r0 = blockIdx.x * 64, c0 = blockIdx.y * 64;
    const int tid = threadIdx.x;
#pragma unroll
    for (int i = 0; i < 4; i++) {
        int f = tid + i * 256;
        int r = f >> 4, c4 = (f & 15) << 2;
        *(float4*)&ts[r][c4] = *(const float4*)(A + (size_t)(r0 + r) * Dd + c0 + c4);
    }
    __syncthreads();
    const int w = tid >> 5, l = tid & 31;
    const int gid = l >> 2, sub = l & 3;

    // A-frag: warp w -> mi=w>>1, k16 j=(w&1)*2+jj
    {
        int mi = w >> 1;
#pragma unroll
        for (int jj = 0; jj < 2; jj++) {
            int j = (w & 1) * 2 + jj;
            int r = mi * 16 + gid, d = j * 16 + 2 * sub;
            uint4 o = make_uint4(
                pk(ts[r][d],         ts[r][d + 1]),
                pk(ts[r + 8][d],     ts[r + 8][d + 1]),
                pk(ts[r][d + 8],     ts[r][d + 9]),
                pk(ts[r + 8][d + 8], ts[r + 8][d + 9]));
            *(uint4*)(g_xA + ((size_t)(r0 / 16 + mi) * (Dd / 16) + (c0 / 16 + j)) * 128 + l * 4) = o;
        }
    }
    // B2-frag: warp w = n8 row; kp 0..1
    {
        int n = w * 8 + gid;
#pragma unroll
        for (int kp = 0; kp < 2; kp++) {
            int d0 = kp * 32 + 2 * sub;
            uint4 o = make_uint4(
                pk(ts[n][d0],      ts[n][d0 + 1]),
                pk(ts[n][d0 + 8],  ts[n][d0 + 9]),
                pk(ts[n][d0 + 16], ts[n][d0 + 17]),
                pk(ts[n][d0 + 24], ts[n][d0 + 25]));
            *(uint4*)(g_xB + ((size_t)(r0 / 8 + w) * (Dd / 32) + (c0 / 32 + kp)) * 128 + l * 4) = o;
        }
    }
}

// ======================================================================
// permW: z 0..2 -> wq/wk/wo in B2; z=3 -> wv in A-frag.
// ======================================================================
__global__ __launch_bounds__(256) void permW(
    const float* __restrict__ W0, const float* __restrict__ W1,
    const float* __restrict__ W2, const float* __restrict__ W3)
{
    __shared__ float ts[64][68];
    const int z = blockIdx.z;
    const float* W = (z == 0) ? W0 : (z == 1) ? W1 : (z == 2) ? W2 : W3;
    const int n0 = blockIdx.x * 64, k0 = blockIdx.y * 64;
    const int tid = threadIdx.x;
#pragma unroll
    for (int i = 0; i < 4; i++) {
        int f = tid + i * 256;
        int r = f >> 4, c4 = (f & 15) << 2;
        *(float4*)&ts[r][c4] = *(const float4*)(W + (size_t)(n0 + r) * Dd + k0 + c4);
    }
    __syncthreads();
    const int w = tid >> 5, l = tid & 31;
    const int gid = l >> 2, sub = l & 3;

    if (z == 3) {
        // A-frag for wv
        int mi = w >> 1;
#pragma unroll
        for (int jj = 0; jj < 2; jj++) {
            int j = (w & 1) * 2 + jj;
            int r = mi * 16 + gid, d = j * 16 + 2 * sub;
            uint4 o = make_uint4(
                pk(ts[r][d],         ts[r][d + 1]),
                pk(ts[r + 8][d],     ts[r + 8][d + 1]),
                pk(ts[r][d + 8],     ts[r][d + 9]),
                pk(ts[r + 8][d + 8], ts[r + 8][d + 9]));
            *(uint4*)(g_wvA + ((size_t)(n0 / 16 + mi) * (Dd / 16) + (k0 / 16 + j)) * 128 + l * 4) = o;
        }
        return;
    }
    uint32_t* D = (z == 0) ? g_wqB : (z == 1) ? g_wkB : g_woB;
    int n = w * 8 + gid;
#pragma unroll
    for (int kp = 0; kp < 2; kp++) {
        int d0 = kp * 32 + 2 * sub;
        uint4 o = make_uint4(
            pk(ts[n][d0],      ts[n][d0 + 1]),
            pk(ts[n][d0 + 8],  ts[n][d0 + 9]),
            pk(ts[n][d0 + 16], ts[n][d0 + 17]),
            pk(ts[n][d0 + 24], ts[n][d0 + 25]));
        *(uint4*)(D + ((size_t)(n0 / 8 + w) * (Dd / 32) + (k0 / 32 + kp)) * 128 + l * 4) = o;
    }
}

// ======================================================================
// GEMM mainloop: CTA 128x128, 256 thr, 8 warps of 32x64.
// A in A-frag, B in B2. 16 chunks of 64 k, 3-stage cp.async.
// smem: A[3][4096] | B[3][4096] words = 96 KB.
// ======================================================================
#define GEMM_SMEM 98304

__device__ __forceinline__ void gemm_main(
    const uint32_t* __restrict__ Ab, const uint32_t* __restrict__ Bp,
    uint32_t* smu, float acc[2][8][4])
{
    const uint32_t sb = smem_u32(smu);
    const int tid = threadIdx.x;
    const int w = tid >> 5, lane = tid & 31;
    const int wm = w >> 1, wn = w & 1;

    const uint32_t* srca[4];
    const uint32_t* srcw[4];
#pragma unroll
    for (int i = 0; i < 4; i++) {
        int f = tid + i * 256;
        int ba = f >> 5, wa = f & 31;
        srca[i] = Ab + ((size_t)(ba >> 2) * (Dd / 16) + (ba & 3)) * 128 + wa * 4;
        int bw = f >> 5, wb = f & 31;
        srcw[i] = Bp + ((size_t)(bw >> 1) * (Dd / 32) + (bw & 1)) * 128 + wb * 4;
    }
#pragma unroll
    for (int mi = 0; mi < 2; mi++)
#pragma unroll
        for (int ni = 0; ni < 8; ni++)
#pragma unroll
            for (int cc = 0; cc < 4; cc++) acc[mi][ni][cc] = 0.0f;

#define GISSUE(c) do { int _b = (c) % 3; \
    _Pragma("unroll") \
    for (int i = 0; i < 4; i++) { int f = tid + i * 256; \
        cp16(sb + (_b * 4096 + f * 4) * 4, srca[i] + (size_t)(c) * 512); \
        cp16(sb + (12288 + _b * 4096 + f * 4) * 4, srcw[i] + (size_t)(c) * 256); } \
    CP_COMMIT(); } while (0)

    GISSUE(0);
    GISSUE(1);
    for (int c = 0; c < 16; c++) {
        if (c + 1 < 16) { CP_WAIT1(); } else { CP_WAIT0(); }
        __syncthreads();
        if (c + 2 < 16) GISSUE(c + 2);
        const uint32_t* As = smu + (c % 3) * 4096;
        const uint32_t* Ws = smu + 12288 + (c % 3) * 4096;
#pragma unroll
        for (int kp = 0; kp < 2; kp++) {
            uint32_t a[2][2][4];
#pragma unroll
            for (int mi = 0; mi < 2; mi++)
#pragma unroll
                for (int kk = 0; kk < 2; kk++) {
                    uint4 av = *((const uint4*)(As + ((wm * 2 + mi) * 4 + kp * 2 + kk) * 128) + lane);
                    a[mi][kk][0] = av.x; a[mi][kk][1] = av.y;
                    a[mi][kk][2] = av.z; a[mi][kk][3] = av.w;
                }
#pragma unroll
            for (int ni = 0; ni < 8; ni++) {
                uint4 bv = *((const uint4*)(Ws + ((wn * 8 + ni) * 2 + kp) * 128) + lane);
                mma16(acc[0][ni], a[0][0], bv.x, bv.y);
                mma16(acc[1][ni], a[1][0], bv.x, bv.y);
                mma16(acc[0][ni], a[0][1], bv.z, bv.w);
                mma16(acc[1][ni], a[1][1], bv.z, bv.w);
            }
        }
    }
#undef GISSUE
}

// ======================================================================
// Fused qkv projections. z=0: Q + RoPE -> Qp (A-frag per bh).
// z=1: K + RoPE -> Kp (B2). z=2: V transposed -> Vp (B2, k=s, n=d).
// ======================================================================
__global__ void __launch_bounds__(256, 2) gemm_qkv()
{
    extern __shared__ uint32_t smu[];
    const int z = blockIdx.z;
    int row0, col0;
    const uint32_t *Ab, *Bp;
    if (z == 2) {
        row0 = blockIdx.x * 128;                 // over Dd (V out-dim)
        col0 = blockIdx.y * 128;                 // over Mm (s)
        Ab = g_wvA + (size_t)(row0 >> 4) * (Dd / 16) * 128;
        Bp = g_xB  + (size_t)(col0 >> 3) * (Dd / 32) * 128;
    } else {
        row0 = blockIdx.y * 128;                 // over Mm (s)
        col0 = blockIdx.x * 128;                 // over Dd
        Ab = g_xA + (size_t)(row0 >> 4) * (Dd / 16) * 128;
        Bp = ((z == 0) ? g_wqB : g_wkB) + (size_t)(col0 >> 3) * (Dd / 32) * 128;
    }

    float acc[2][8][4];
    gemm_main(Ab, Bp, smu, acc);

    const int tid = threadIdx.x;
    const int w = tid >> 5, lane = tid & 31;
    const int gid = lane >> 2, sub = lane & 3;
    const int wm = w >> 1, wn = w & 1;

    if (z == 2) {
        // Vp (B2): words lane*4 = frags of k16 blocks 2sp, 2sp+1
        const int bb = col0 >> 11;
        const int sB = (col0 & 2047) + wn * 64;
        const int dW = row0 + wm * 32;
        const int bh = bb * 16 + (dW >> 6);
        const int hd8b = (dW & 63) >> 3;
        uint32_t* dst = g_vp + (size_t)bh * 65536;
#pragma unroll
        for (int d8 = 0; d8 < 4; d8++) {
            int mi = d8 >> 1, hh = d8 & 1;
#pragma unroll
            for (int sp = 0; sp < 2; sp++) {
                uint4 o = make_uint4(
                    pk(acc[mi][4 * sp][2 * hh],     acc[mi][4 * sp][2 * hh + 1]),
                    pk(acc[mi][4 * sp + 1][2 * hh], acc[mi][4 * sp + 1][2 * hh + 1]),
                    pk(acc[mi][4 * sp + 2][2 * hh], acc[mi][4 * sp + 2][2 * hh + 1]),
                    pk(acc[mi][4 * sp + 3][2 * hh], acc[mi][4 * sp + 3][2 * hh + 1]));
                *(uint4*)(dst + (((size_t)(sB >> 5) + sp) * 8 + hd8b + d8) * 128 + lane * 4) = o;
            }
        }
        return;
    }

    // z 0/1: RoPE in registers (pair d, d+32 = acc[..][ni], acc[..][ni+4])
    const int bb = row0 >> 11;
    const int sB = (row0 & 2047) + wm * 32;
    const int bh = bb * 16 + (col0 >> 6) + wn;
#pragma unroll
    for (int mi = 0; mi < 2; mi++) {
#pragma unroll
        for (int hh = 0; hh < 2; hh++) {
            int s = sB + mi * 16 + gid + 8 * hh;
#pragma unroll
            for (int ni = 0; ni < 4; ni++) {
                float2 c2 = *(const float2*)&g_cos[s * 32 + ni * 8 + 2 * sub];
                float2 s2 = *(const float2*)&g_sin[s * 32 + ni * 8 + 2 * sub];
                {
                    int cc = 2 * hh;
                    float x1 = acc[mi][ni][cc], x2 = acc[mi][ni + 4][cc];
                    acc[mi][ni][cc]     = x1 * c2.x - x2 * s2.x;
                    acc[mi][ni + 4][cc] = x2 * c2.x + x1 * s2.x;
                }
                {
                    int cc = 2 * hh + 1;
                    float x1 = acc[mi][ni][cc], x2 = acc[mi][ni + 4][cc];
                    acc[mi][ni][cc]     = x1 * c2.y - x2 * s2.y;
                    acc[mi][ni + 4][cc] = x2 * c2.y + x1 * s2.y;
                }
            }
        }
    }

    if (z == 0) {
        uint32_t* dst = g_qp + (size_t)bh * 65536;
#pragma unroll
        for (int mi = 0; mi < 2; mi++) {
#pragma unroll
            for (int j = 0; j < 4; j++) {
                uint4 o = make_uint4(
                    pk(acc[mi][2 * j][0],     acc[mi][2 * j][1]),
                    pk(acc[mi][2 * j][2],     acc[mi][2 * j][3]),
                    pk(acc[mi][2 * j + 1][0], acc[mi][2 * j + 1][1]),
                    pk(acc[mi][2 * j + 1][2], acc[mi][2 * j + 1][3]));
                *(uint4*)(dst + ((size_t)((sB >> 4) + mi) * 4 + j) * 128 + lane * 4) = o;
            }
        }
    } else {
        // Kp (B2): superblock (s8, k32=jp)
        uint32_t* dst = g_kp + (size_t)bh * 65536;
#pragma unroll
        for (int s8 = 0; s8 < 4; s8++) {
            int mi = s8 >> 1, hh = s8 & 1;
#pragma unroll
            for (int jp = 0; jp < 2; jp++) {
                uint4 o = make_uint4(
                    pk(acc[mi][4 * jp][2 * hh],     acc[mi][4 * jp][2 * hh + 1]),
                    pk(acc[mi][4 * jp + 1][2 * hh], acc[mi][4 * jp + 1][2 * hh + 1]),
                    pk(acc[mi][4 * jp + 2][2 * hh], acc[mi][4 * jp + 2][2 * hh + 1]),
                    pk(acc[mi][4 * jp + 3][2 * hh], acc[mi][4 * jp + 3][2 * hh + 1]));
                *(uint4*)(dst + (((size_t)((sB >> 3) + s8)) * 2 + jp) * 128 + lane * 4) = o;
            }
        }
    }
}

// ======================================================================
// Output projection: out = Op @ wo^T (fp32 row-major result)
// ======================================================================
__global__ void __launch_bounds__(256, 2) gemm_o(float* __restrict__ C)
{
    extern __shared__ uint32_t smu[];
    const int row0 = blockIdx.y * 128, col0 = blockIdx.x * 128;
    const uint32_t* Ab = g_op  + (size_t)(row0 >> 4) * (Dd / 16) * 128;
    const uint32_t* Bp = g_woB + (size_t)(col0 >> 3) * (Dd / 32) * 128;

    float acc[2][8][4];
    gemm_main(Ab, Bp, smu, acc);

    const int tid = threadIdx.x;
    const int w = tid >> 5, lane = tid & 31;
    const int gid = lane >> 2, sub = lane & 3;
    const int wm = w >> 1, wn = w & 1;
#pragma unroll
    for (int mi = 0; mi < 2; mi++) {
        int row = row0 + wm * 32 + mi * 16 + gid;
#pragma unroll
        for (int ni = 0; ni < 8; ni++) {
            int col = col0 + wn * 64 + ni * 8 + 2 * sub;
            *(float2*)(C + (size_t)row * Dd + col) =
                make_float2(acc[mi][ni][0], acc[mi][ni][1]);
            *(float2*)(C + (size_t)(row + 8) * Dd + col) =
                make_float2(acc[mi][ni][2], acc[mi][ni][3]);
        }
    }
}

// ======================================================================
// Flash attention, causal, fp16 m16n8k16, B2-frag K/V (all LDS.128).
// PAIRED q-tiles {NT-1-bx, bx}: constant 34 iterations per CTA.
// 4 warps x (32 rows, 64 cols). 3-stage cp.async on K,V.
// ======================================================================
#define FQ 0
#define FK(b) (4096 + (b)*2048)
#define FV(b) (10240 + (b)*2048)
#define FA_SMEM (16384*4)
#define SCL 0.180336877f    // 0.125 * log2(e)
#define NT (Ss/128)         // 16 q-tiles per (b,h)

__global__ void __launch_bounds__(128, 2) flash_tc()
{
    extern __shared__ uint32_t smu[];
    const uint32_t sb = smem_u32(smu);

    const int tid = threadIdx.x;
    const int w = tid >> 5, lane = tid & 31;
    const int gid = lane >> 2, sub = lane & 3;

    const int bh = blockIdx.y;
    const int bb = bh >> 4, h = bh & 15;

    const size_t bho = (size_t)bh * 65536;
    const uint32_t* Kg = g_kp + bho;
    const uint32_t* Vg = g_vp + bho;

#pragma unroll
    for (int t = 0; t < 2; t++) {
        const int qt = t ? (int)blockIdx.x : (NT - 1 - (int)blockIdx.x);
        const int q0 = qt * 128;
        const uint32_t* Qg = g_qp + bho + (size_t)qt * 4096;
        const int nkt = 2 * qt + 2;

        // ---- prolog: Q, then K0/V0, K1/V1 ----
#pragma unroll
        for (int i = 0; i < 8; i++) {
            int f = tid + i * 128;
            cp16(sb + (FQ + f * 4) * 4, Qg + f * 4);
        }
        CP_COMMIT();
#pragma unroll
        for (int i = 0; i < 4; i++) {
            int f = tid + i * 128;
            cp16(sb + (FK(0) + f * 4) * 4, Kg + f * 4);
            cp16(sb + (FV(0) + f * 4) * 4, Vg + f * 4);
        }
        CP_COMMIT();
#pragma unroll
        for (int i = 0; i < 4; i++) {
            int f = tid + i * 128;
            cp16(sb + (FK(1) + f * 4) * 4, Kg + 2048 + f * 4);
            cp16(sb + (FV(1) + f * 4) * 4, Vg + 2048 + f * 4);
        }
        CP_COMMIT();

        CP_WAIT2();          // Q resident
        __syncthreads();

        uint32_t qf[2][4][4];
#pragma unroll
        for (int mi = 0; mi < 2; mi++)
#pragma unroll
            for (int ks = 0; ks < 4; ks++) {
                uint4 av = *((const uint4*)(smu + FQ + ((w * 2 + mi) * 4 + ks) * 128) + lane);
                qf[mi][ks][0] = av.x; qf[mi][ks][1] = av.y;
                qf[mi][ks][2] = av.z; qf[mi][ks][3] = av.w;
            }

        float m_i[2][2], l_i[2][2];
        float acc[2][8][4];
#pragma unroll
        for (int mi = 0; mi < 2; mi++) {
            m_i[mi][0] = -1e30f; m_i[mi][1] = -1e30f;
            l_i[mi][0] = 0.0f;   l_i[mi][1] = 0.0f;
#pragma unroll
            for (int ni = 0; ni < 8; ni++)
#pragma unroll
                for (int cc = 0; cc < 4; cc++) acc[mi][ni][cc] = 0.0f;
        }

        for (int kb = 0; kb < nkt; kb++) {
            const int b = kb % 3;
            const uint32_t* Ks = smu + FK(b);
            const uint32_t* Vs = smu + FV(b);

            if (kb + 1 < nkt) { CP_WAIT1(); } else { CP_WAIT0(); }
            __syncthreads();

            if (kb + 2 < nkt) {
                const int b2 = (kb + 2) % 3;
                const uint32_t* Kn = Kg + (size_t)(kb + 2) * 2048;
                const uint32_t* Vn = Vg + (size_t)(kb + 2) * 2048;
#pragma unroll
                for (int i = 0; i < 4; i++) {
                    int f = tid + i * 128;
                    cp16(sb + (FK(b2) + f * 4) * 4, Kn + f * 4);
                    cp16(sb + (FV(b2) + f * 4) * 4, Vn + f * 4);
                }
                CP_COMMIT();
            }

            if (kb == 2 * qt + 1 && w < 2) continue;   // fully-masked warps

            // ---- S = Q K^T (K in B2: one LDS.128 -> two k16 frags) ----
            float s[2][8][4];
#pragma unroll
            for (int mi = 0; mi < 2; mi++)
#pragma unroll
                for (int ni = 0; ni < 8; ni++)
#pragma unroll
                    for (int cc = 0; cc < 4; cc++) s[mi][ni][cc] = 0.0f;

#pragma unroll
            for (int kp = 0; kp < 2; kp++) {
#pragma unroll
                for (int ni = 0; ni < 8; ni++) {
                    uint4 bv = *((const uint4*)(Ks + (ni * 2 + kp) * 128) + lane);
                    mma16(s[0][ni], qf[0][2 * kp],     bv.x, bv.y);
                    mma16(s[1][ni], qf[1][2 * kp],     bv.x, bv.y);
                    mma16(s[0][ni], qf[0][2 * kp + 1], bv.z, bv.w);
                    mma16(s[1][ni], qf[1][2 * kp + 1], bv.z, bv.w);
                }
            }

            // ---- scale + causal mask + online softmax (log2 domain) ----
            const int k0 = kb * 64;
            const bool mt = (kb >= 2 * qt);
            uint32_t pa[2][4][4];
#pragma unroll
            for (int mi = 0; mi < 2; mi++) {
                const int r0g = q0 + w * 32 + mi * 16 + gid;
                float rmax[2] = {-1e30f, -1e30f};
#pragma unroll
                for (int ni = 0; ni < 8; ni++) {
                    int colb = k0 + ni * 8 + 2 * sub;
#pragma unroll
                    for (int cc = 0; cc < 4; cc++) {
                        float sv = s[mi][ni][cc] * SCL;
                        if (mt) {
                            int row = r0g + ((cc >> 1) << 3);
                            int col = colb + (cc & 1);
                            if (col > row) sv = -1e30f;
                        }
                        s[mi][ni][cc] = sv;
                        rmax[cc >> 1] = fmaxf(rmax[cc >> 1], sv);
                    }
                }
#pragma unroll
                for (int o = 1; o <= 2; o <<= 1) {
                    rmax[0] = fmaxf(rmax[0], __shfl_xor_sync(0xffffffffu, rmax[0], o));
                    rmax[1] = fmaxf(rmax[1], __shfl_xor_sync(0xffffffffu, rmax[1], o));
                }
                float mnew0 = fmaxf(m_i[mi][0], rmax[0]);
                float mnew1 = fmaxf(m_i[mi][1], rmax[1]);
                float corr0 = exp2f(m_i[mi][0] - mnew0);
                float corr1 = exp2f(m_i[mi][1] - mnew1);
                m_i[mi][0] = mnew0; m_i[mi][1] = mnew1;

                float rsum[2] = {0.0f, 0.0f};
#pragma unroll
                for (int ni = 0; ni < 8; ni++) {
                    s[mi][ni][0] = exp2f(s[mi][ni][0] - mnew0);
                    s[mi][ni][1] = exp2f(s[mi][ni][1] - mnew0);
                    s[mi][ni][2] = exp2f(s[mi][ni][2] - mnew1);
                    s[mi][ni][3] = exp2f(s[mi][ni][3] - mnew1);
                    rsum[0] += s[mi][ni][0] + s[mi][ni][1];
                    rsum[1] += s[mi][ni][2] + s[mi][ni][3];
                    acc[mi][ni][0] *= corr0; acc[mi][ni][1] *= corr0;
                    acc[mi][ni][2] *= corr1; acc[mi][ni][3] *= corr1;
                }
#pragma unroll
                for (int o = 1; o <= 2; o <<= 1) {
                    rsum[0] += __shfl_xor_sync(0xffffffffu, rsum[0], o);
                    rsum[1] += __shfl_xor_sync(0xffffffffu, rsum[1], o);
                }
                l_i[mi][0] = l_i[mi][0] * corr0 + rsum[0];
                l_i[mi][1] = l_i[mi][1] * corr1 + rsum[1];

                // P -> A-fragments directly in registers
#pragma unroll
                for (int j = 0; j < 4; j++) {
                    pa[mi][j][0] = pk(s[mi][2 * j][0],     s[mi][2 * j][1]);
                    pa[mi][j][1] = pk(s[mi][2 * j][2],     s[mi][2 * j][3]);
                    pa[mi][j][2] = pk(s[mi][2 * j + 1][0], s[mi][2 * j + 1][1]);
                    pa[mi][j][3] = pk(s[mi][2 * j + 1][2], s[mi][2 * j + 1][3]);
                }
            }

            // ---- O += P V (V in B2) ----
#pragma unroll
            for (int jp = 0; jp < 2; jp++) {
#pragma unroll
                for (int ni = 0; ni < 8; ni++) {
                    uint4 bv = *((const uint4*)(Vs + (jp * 8 + ni) * 128) + lane);
                    mma16(acc[0][ni], pa[0][2 * jp],     bv.x, bv.y);
                    mma16(acc[1][ni], pa[1][2 * jp],     bv.x, bv.y);
                    mma16(acc[0][ni], pa[0][2 * jp + 1], bv.z, bv.w);
                    mma16(acc[1][ni], pa[1][2 * jp + 1], bv.z, bv.w);
                }
            }
        }

        // ---- normalize, write Op in GLOBAL fp16 A-frag layout ----
#pragma unroll
        for (int mi = 0; mi < 2; mi++) {
            int m16 = bb * 128 + qt * 8 + w * 2 + mi;
            float inv0 = 1.0f / l_i[mi][0];
            float inv1 = 1.0f / l_i[mi][1];
#pragma unroll
            for (int j = 0; j < 4; j++) {
                uint4 o = make_uint4(
                    pk(acc[mi][2 * j][0] * inv0,     acc[mi][2 * j][1] * inv0),
                    pk(acc[mi][2 * j][2] * inv1,     acc[mi][2 * j][3] * inv1),
                    pk(acc[mi][2 * j + 1][0] * inv0, acc[mi][2 * j + 1][1] * inv0),
                    pk(acc[mi][2 * j + 1][2] * inv1, acc[mi][2 * j + 1][3] * inv1));
                *(uint4*)(g_op + ((size_t)m16 * (Dd / 16) + h * 4 + j) * 128 + lane * 4) = o;
            }
        }
        __syncthreads();   // smem reuse safe before next tile's prolog
    }
}

// ======================================================================
// Launch
// ======================================================================
extern "C" void kernel_launch(void* const* d_in, const int* in_sizes, int n_in,
                              void* d_out, int out_size)
{
    const float* x  = (const float*)d_in[0];
    const float* wq = (const float*)d_in[1];
    const float* wk = (const float*)d_in[2];
    const float* wv = (const float*)d_in[3];
    const float* wo = (const float*)d_in[4];
    float* out = (float*)d_out;

    float *tc, *ts;
    cudaGetSymbolAddress((void**)&tc, g_cos);
    cudaGetSymbolAddress((void**)&ts, g_sin);

    cudaFuncSetAttribute(gemm_qkv, cudaFuncAttributeMaxDynamicSharedMemorySize, GEMM_SMEM);
    cudaFuncSetAttribute(gemm_o,   cudaFuncAttributeMaxDynamicSharedMemorySize, GEMM_SMEM);
    cudaFuncSetAttribute(flash_tc, cudaFuncAttributeMaxDynamicSharedMemorySize, FA_SMEM);

    // 0) tables + operand permutes (2 launches)
    build_tab<<<(Ss * 32) / 256, 256>>>(tc, ts);
    permX<<<dim3(Mm / 64, Dd / 64), 256>>>(x);
    permW<<<dim3(Dd / 64, Dd / 64, 4), 256>>>(wq, wk, wo, wv);

    // 1) fused q/k/v projections + RoPE + frag-permute epilogues
    gemm_qkv<<<dim3(Dd / 128, Mm / 128, 3), 256, GEMM_SMEM>>>();

    // 2) causal flash attention (balanced paired q-tiles)
    flash_tc<<<dim3(NT / 2, Bb * Hh), 128, FA_SMEM>>>();

    // 3) output projection
    gemm_o<<<dim3(Dd / 128, Mm / 128), 256, GEMM_SMEM>>>(out);
}

// round 12
// speedup vs baseline: 1.0353x; 1.0353x over previous
#include <cuda_runtime.h>
#include <cuda_fp16.h>
#include <math.h>
#include <stdint.h>

// Problem constants
#define Bb 2
#define Ss 2048
#define Dd 1024
#define Hh 16
#define HDh 64
#define Mm (Bb*Ss)   // 4096

// Scratch (device globals), all fp16-packed uint32 unless noted
// B2 layout: superblocks (n8, k32) of 128 words; lane l owns l*4+{0..3} =
//   [b0(k16 even), b1(even), b0(k16 odd), b1(odd)]
__device__ uint32_t g_xA[Mm*Dd/2];     // x, A-frag
__device__ uint32_t g_xB[Mm*Dd/2];     // x, B2-frag (n=s)
__device__ uint32_t g_wqB[Dd*Dd/2];    // B2
__device__ uint32_t g_wkB[Dd*Dd/2];    // B2
__device__ uint32_t g_woB[Dd*Dd/2];    // B2
__device__ uint32_t g_wvA[Dd*Dd/2];    // wv, A-frag (for transposed V gemm)
__device__ uint32_t g_qp[Mm*Dd/2];     // Q per (b,h), A-frag
__device__ uint32_t g_kp[Mm*Dd/2];     // K per (b,h), B2 (n=s, k=d)
__device__ uint32_t g_vp[Mm*Dd/2];     // V per (b,h), B2 (k=s, n=d)
__device__ uint32_t g_op[Mm*Dd/2];     // attn out, global A-frag
__device__ float    g_cos[Ss*32];
__device__ float    g_sin[Ss*32];

// ======================================================================
// Helpers
// ======================================================================
__device__ __forceinline__ uint32_t smem_u32(const void* p) {
    uint32_t a;
    asm("{ .reg .u64 t; cvta.to.shared.u64 t, %1; cvt.u32.u64 %0, t; }"
        : "=r"(a) : "l"(p));
    return a;
}
__device__ __forceinline__ uint32_t pk(float a, float b) {
    __half2 h = __floats2half2_rn(a, b);
    return *reinterpret_cast<uint32_t*>(&h);
}
__device__ __forceinline__ void mma16(float* d, const uint32_t* a,
                                      uint32_t b0, uint32_t b1) {
    asm volatile(
        "mma.sync.aligned.m16n8k16.row.col.f32.f16.f16.f32 "
        "{%0,%1,%2,%3}, {%4,%5,%6,%7}, {%8,%9}, {%0,%1,%2,%3};"
        : "+f"(d[0]), "+f"(d[1]), "+f"(d[2]), "+f"(d[3])
        : "r"(a[0]), "r"(a[1]), "r"(a[2]), "r"(a[3]), "r"(b0), "r"(b1));
}
__device__ __forceinline__ void cp16(uint32_t dst, const void* src) {
    asm volatile("cp.async.cg.shared.global [%0], [%1], 16;"
                 :: "r"(dst), "l"(src) : "memory");
}
#define CP_COMMIT() asm volatile("cp.async.commit_group;" ::: "memory")
#define CP_WAIT0()  asm volatile("cp.async.wait_group 0;" ::: "memory")
#define CP_WAIT1()  asm volatile("cp.async.wait_group 1;" ::: "memory")
#define CP_WAIT2()  asm volatile("cp.async.wait_group 2;" ::: "memory")

// ======================================================================
// prep: ONE kernel for RoPE tables + all operand permutes.
// z=0: x -> xA (A-frag) + xB (B2) + a 64-entry table slice per CTA.
// z=1: bx>>4 selects {wq,wk,wo,wv}; first three -> B2, wv -> A-frag.
// ======================================================================
__global__ __launch_bounds__(256) void prep(
    const float* __restrict__ x,
    const float* __restrict__ wq, const float* __restrict__ wk,
    const float* __restrict__ wo, const float* __restrict__ wv)
{
    __shared__ float ts[64][68];
    const int tid = threadIdx.x;
    const int w = tid >> 5, l = tid & 31;
    const int gid = l >> 2, sub = l & 3;

    if (blockIdx.z == 0) {
        // RoPE table slice: 1024 CTAs x 64 entries = 65536
        if (tid < 64) {
            int idx = (int)(blockIdx.x * 16 + blockIdx.y) * 64 + tid;
            int s = idx >> 5, i = idx & 31;
            double inv = pow(10000.0, -((double)(2 * i)) / (double)HDh);
            double sd, cd;
            sincos((double)s * inv, &sd, &cd);
            g_cos[idx] = (float)cd;
            g_sin[idx] = (float)sd;
        }
        const int r0 = blockIdx.x * 64, c0 = blockIdx.y * 64;
#pragma unroll
        for (int i = 0; i < 4; i++) {
            int f = tid + i * 256;
            int r = f >> 4, c4 = (f & 15) << 2;
            *(float4*)&ts[r][c4] = *(const float4*)(x + (size_t)(r0 + r) * Dd + c0 + c4);
        }
        __syncthreads();
        // A-frag
        {
            int mi = w >> 1;
#pragma unroll
            for (int jj = 0; jj < 2; jj++) {
                int j = (w & 1) * 2 + jj;
                int r = mi * 16 + gid, d = j * 16 + 2 * sub;
                uint4 o = make_uint4(
                    pk(ts[r][d],         ts[r][d + 1]),
                    pk(ts[r + 8][d],     ts[r + 8][d + 1]),
                    pk(ts[r][d + 8],     ts[r][d + 9]),
                    pk(ts[r + 8][d + 8], ts[r + 8][d + 9]));
                *(uint4*)(g_xA + ((size_t)(r0 / 16 + mi) * (Dd / 16) + (c0 / 16 + j)) * 128 + l * 4) = o;
            }
        }
        // B2-frag
        {
            int n = w * 8 + gid;
#pragma unroll
            for (int kp = 0; kp < 2; kp++) {
                int d0 = kp * 32 + 2 * sub;
                uint4 o = make_uint4(
                    pk(ts[n][d0],      ts[n][d0 + 1]),
                    pk(ts[n][d0 + 8],  ts[n][d0 + 9]),
                    pk(ts[n][d0 + 16], ts[n][d0 + 17]),
                    pk(ts[n][d0 + 24], ts[n][d0 + 25]));
                *(uint4*)(g_xB + ((size_t)(r0 / 8 + w) * (Dd / 32) + (c0 / 32 + kp)) * 128 + l * 4) = o;
            }
        }
        return;
    }

    // z == 1: weights
    const int wsel = blockIdx.x >> 4;
    const float* W = (wsel == 0) ? wq : (wsel == 1) ? wk : (wsel == 2) ? wo : wv;
    const int n0 = (blockIdx.x & 15) * 64, k0 = blockIdx.y * 64;
#pragma unroll
    for (int i = 0; i < 4; i++) {
        int f = tid + i * 256;
        int r = f >> 4, c4 = (f & 15) << 2;
        *(float4*)&ts[r][c4] = *(const float4*)(W + (size_t)(n0 + r) * Dd + k0 + c4);
    }
    __syncthreads();

    if (wsel == 3) {
        // wv -> A-frag
        int mi = w >> 1;
#pragma unroll
        for (int jj = 0; jj < 2; jj++) {
            int j = (w & 1) * 2 + jj;
            int r = mi * 16 + gid, d = j * 16 + 2 * sub;
            uint4 o = make_uint4(
                pk(ts[r][d],         ts[r][d + 1]),
                pk(ts[r + 8][d],     ts[r + 8][d + 1]),
                pk(ts[r][d + 8],     ts[r][d + 9]),
                pk(ts[r + 8][d + 8], ts[r + 8][d + 9]));
            *(uint4*)(g_wvA + ((size_t)(n0 / 16 + mi) * (Dd / 16) + (k0 / 16 + j)) * 128 + l * 4) = o;
        }
        return;
    }
    uint32_t* D = (wsel == 0) ? g_wqB : (wsel == 1) ? g_wkB : g_woB;
    int n = w * 8 + gid;
#pragma unroll
    for (int kp = 0; kp < 2; kp++) {
        int d0 = kp * 32 + 2 * sub;
        uint4 o = make_uint4(
            pk(ts[n][d0],      ts[n][d0 + 1]),
            pk(ts[n][d0 + 8],  ts[n][d0 + 9]),
            pk(ts[n][d0 + 16], ts[n][d0 + 17]),
            pk(ts[n][d0 + 24], ts[n][d0 + 25]));
        *(uint4*)(D + ((size_t)(n0 / 8 + w) * (Dd / 32) + (k0 / 32 + kp)) * 128 + l * 4) = o;
    }
}

// ======================================================================
// GEMM mainloop: CTA 128x128, 256 thr, 8 warps of 32x64.
// A in A-frag, B in B2. 16 chunks of 64 k, 3-stage cp.async.
// smem: A[3][4096] | B[3][4096] words = 96 KB.
// ======================================================================
#define GEMM_SMEM 98304

__device__ __forceinline__ void gemm_main(
    const uint32_t* __restrict__ Ab, const uint32_t* __restrict__ Bp,
    uint32_t* smu, float acc[2][8][4])
{
    const uint32_t sb = smem_u32(smu);
    const int tid = threadIdx.x;
    const int w = tid >> 5, lane = tid & 31;
    const int wm = w >> 1, wn = w & 1;

    const uint32_t* srca[4];
    const uint32_t* srcw[4];
#pragma unroll
    for (int i = 0; i < 4; i++) {
        int f = tid + i * 256;
        int ba = f >> 5, wa = f & 31;
        srca[i] = Ab + ((size_t)(ba >> 2) * (Dd / 16) + (ba & 3)) * 128 + wa * 4;
        int bw = f >> 5, wb = f & 31;
        srcw[i] = Bp + ((size_t)(bw >> 1) * (Dd / 32) + (bw & 1)) * 128 + wb * 4;
    }
#pragma unroll
    for (int mi = 0; mi < 2; mi++)
#pragma unroll
        for (int ni = 0; ni < 8; ni++)
#pragma unroll
            for (int cc = 0; cc < 4; cc++) acc[mi][ni][cc] = 0.0f;

#define GISSUE(c) do { int _b = (c) % 3; \
    _Pragma("unroll") \
    for (int i = 0; i < 4; i++) { int f = tid + i * 256; \
        cp16(sb + (_b * 4096 + f * 4) * 4, srca[i] + (size_t)(c) * 512); \
        cp16(sb + (12288 + _b * 4096 + f * 4) * 4, srcw[i] + (size_t)(c) * 256); } \
    CP_COMMIT(); } while (0)

    GISSUE(0);
    GISSUE(1);
    for (int c = 0; c < 16; c++) {
        if (c + 1 < 16) { CP_WAIT1(); } else { CP_WAIT0(); }
        __syncthreads();
        if (c + 2 < 16) GISSUE(c + 2);
        const uint32_t* As = smu + (c % 3) * 4096;
        const uint32_t* Ws = smu + 12288 + (c % 3) * 4096;
#pragma unroll
        for (int kp = 0; kp < 2; kp++) {
            uint32_t a[2][2][4];
#pragma unroll
            for (int mi = 0; mi < 2; mi++)
#pragma unroll
                for (int kk = 0; kk < 2; kk++) {
                    uint4 av = *((const uint4*)(As + ((wm * 2 + mi) * 4 + kp * 2 + kk) * 128) + lane);
                    a[mi][kk][0] = av.x; a[mi][kk][1] = av.y;
                    a[mi][kk][2] = av.z; a[mi][kk][3] = av.w;
                }
#pragma unroll
            for (int ni = 0; ni < 8; ni++) {
                uint4 bv = *((const uint4*)(Ws + ((wn * 8 + ni) * 2 + kp) * 128) + lane);
                mma16(acc[0][ni], a[0][0], bv.x, bv.y);
                mma16(acc[1][ni], a[1][0], bv.x, bv.y);
                mma16(acc[0][ni], a[0][1], bv.z, bv.w);
                mma16(acc[1][ni], a[1][1], bv.z, bv.w);
            }
        }
    }
#undef GISSUE
}

// ======================================================================
// Fused qkv projections. z=0: Q + RoPE -> Qp (A-frag per bh).
// z=1: K + RoPE -> Kp (B2). z=2: V transposed -> Vp (B2, k=s, n=d).
// ======================================================================
__global__ void __launch_bounds__(256, 2) gemm_qkv()
{
    extern __shared__ uint32_t smu[];
    const int z = blockIdx.z;
    int row0, col0;
    const uint32_t *Ab, *Bp;
    if (z == 2) {
        row0 = blockIdx.x * 128;                 // over Dd (V out-dim)
        col0 = blockIdx.y * 128;                 // over Mm (s)
        Ab = g_wvA + (size_t)(row0 >> 4) * (Dd / 16) * 128;
        Bp = g_xB  + (size_t)(col0 >> 3) * (Dd / 32) * 128;
    } else {
        row0 = blockIdx.y * 128;                 // over Mm (s)
        col0 = blockIdx.x * 128;                 // over Dd
        Ab = g_xA + (size_t)(row0 >> 4) * (Dd / 16) * 128;
        Bp = ((z == 0) ? g_wqB : g_wkB) + (size_t)(col0 >> 3) * (Dd / 32) * 128;
    }

    float acc[2][8][4];
    gemm_main(Ab, Bp, smu, acc);

    const int tid = threadIdx.x;
    const int w = tid >> 5, lane = tid & 31;
    const int gid = lane >> 2, sub = lane & 3;
    const int wm = w >> 1, wn = w & 1;

    if (z == 2) {
        const int bb = col0 >> 11;
        const int sB = (col0 & 2047) + wn * 64;
        const int dW = row0 + wm * 32;
        const int bh = bb * 16 + (dW >> 6);
        const int hd8b = (dW & 63) >> 3;
        uint32_t* dst = g_vp + (size_t)bh * 65536;
#pragma unroll
        for (int d8 = 0; d8 < 4; d8++) {
            int mi = d8 >> 1, hh = d8 & 1;
#pragma unroll
            for (int sp = 0; sp < 2; sp++) {
                uint4 o = make_uint4(
                    pk(acc[mi][4 * sp][2 * hh],     acc[mi][4 * sp][2 * hh + 1]),
                    pk(acc[mi][4 * sp + 1][2 * hh], acc[mi][4 * sp + 1][2 * hh + 1]),
                    pk(acc[mi][4 * sp + 2][2 * hh], acc[mi][4 * sp + 2][2 * hh + 1]),
                    pk(acc[mi][4 * sp + 3][2 * hh], acc[mi][4 * sp + 3][2 * hh + 1]));
                *(uint4*)(dst + (((size_t)(sB >> 5) + sp) * 8 + hd8b + d8) * 128 + lane * 4) = o;
            }
        }
        return;
    }

    // z 0/1: RoPE in registers (pair d, d+32 = acc[..][ni], acc[..][ni+4])
    const int bb = row0 >> 11;
    const int sB = (row0 & 2047) + wm * 32;
    const int bh = bb * 16 + (col0 >> 6) + wn;
#pragma unroll
    for (int mi = 0; mi < 2; mi++) {
#pragma unroll
        for (int hh = 0; hh < 2; hh++) {
            int s = sB + mi * 16 + gid + 8 * hh;
#pragma unroll
            for (int ni = 0; ni < 4; ni++) {
                float2 c2 = *(const float2*)&g_cos[s * 32 + ni * 8 + 2 * sub];
                float2 s2 = *(const float2*)&g_sin[s * 32 + ni * 8 + 2 * sub];
                {
                    int cc = 2 * hh;
                    float x1 = acc[mi][ni][cc], x2 = acc[mi][ni + 4][cc];
                    acc[mi][ni][cc]     = x1 * c2.x - x2 * s2.x;
                    acc[mi][ni + 4][cc] = x2 * c2.x + x1 * s2.x;
                }
                {
                    int cc = 2 * hh + 1;
                    float x1 = acc[mi][ni][cc], x2 = acc[mi][ni + 4][cc];
                    acc[mi][ni][cc]     = x1 * c2.y - x2 * s2.y;
                    acc[mi][ni + 4][cc] = x2 * c2.y + x1 * s2.y;
                }
            }
        }
    }

    if (z == 0) {
        uint32_t* dst = g_qp + (size_t)bh * 65536;
#pragma unroll
        for (int mi = 0; mi < 2; mi++) {
#pragma unroll
            for (int j = 0; j < 4; j++) {
                uint4 o = make_uint4(
                    pk(acc[mi][2 * j][0],     acc[mi][2 * j][1]),
                    pk(acc[mi][2 * j][2],     acc[mi][2 * j][3]),
                    pk(acc[mi][2 * j + 1][0], acc[mi][2 * j + 1][1]),
                    pk(acc[mi][2 * j + 1][2], acc[mi][2 * j + 1][3]));
                *(uint4*)(dst + ((size_t)((sB >> 4) + mi) * 4 + j) * 128 + lane * 4) = o;
            }
        }
    } else {
        uint32_t* dst = g_kp + (size_t)bh * 65536;
#pragma unroll
        for (int s8 = 0; s8 < 4; s8++) {
            int mi = s8 >> 1, hh = s8 & 1;
#pragma unroll
            for (int jp = 0; jp < 2; jp++) {
                uint4 o = make_uint4(
                    pk(acc[mi][4 * jp][2 * hh],     acc[mi][4 * jp][2 * hh + 1]),
                    pk(acc[mi][4 * jp + 1][2 * hh], acc[mi][4 * jp + 1][2 * hh + 1]),
                    pk(acc[mi][4 * jp + 2][2 * hh], acc[mi][4 * jp + 2][2 * hh + 1]),
                    pk(acc[mi][4 * jp + 3][2 * hh], acc[mi][4 * jp + 3][2 * hh + 1]));
                *(uint4*)(dst + (((size_t)((sB >> 3) + s8)) * 2 + jp) * 128 + lane * 4) = o;
            }
        }
    }
}

// ======================================================================
// Output projection: out = Op @ wo^T (fp32 row-major result)
// ======================================================================
__global__ void __launch_bounds__(256, 2) gemm_o(float* __restrict__ C)
{
    extern __shared__ uint32_t smu[];
    const int row0 = blockIdx.y * 128, col0 = blockIdx.x * 128;
    const uint32_t* Ab = g_op  + (size_t)(row0 >> 4) * (Dd / 16) * 128;
    const uint32_t* Bp = g_woB + (size_t)(col0 >> 3) * (Dd / 32) * 128;

    float acc[2][8][4];
    gemm_main(Ab, Bp, smu, acc);

    const int tid = threadIdx.x;
    const int w = tid >> 5, lane = tid & 31;
    const int gid = lane >> 2, sub = lane & 3;
    const int wm = w >> 1, wn = w & 1;
#pragma unroll
    for (int mi = 0; mi < 2; mi++) {
        int row = row0 + wm * 32 + mi * 16 + gid;
#pragma unroll
        for (int ni = 0; ni < 8; ni++) {
            int col = col0 + wn * 64 + ni * 8 + 2 * sub;
            *(float2*)(C + (size_t)row * Dd + col) =
                make_float2(acc[mi][ni][0], acc[mi][ni][1]);
            *(float2*)(C + (size_t)(row + 8) * Dd + col) =
                make_float2(acc[mi][ni][2], acc[mi][ni][3]);
        }
    }
}

// ======================================================================
// Flash attention, causal, fp16 m16n8k16, B2-frag K/V.
// 8 warps (256 thr), each warp 16 q-rows x 64 cols -> ~120 regs,
// 2 CTA/SM = 16 warps/SM (2x occupancy vs 4-warp version).
// PAIRED q-tiles {NT-1-bx, bx}: constant 34 iterations per CTA.
// 3-stage cp.async on K,V. smem: Q 16KB | K[3][8KB] | V[3][8KB] = 64KB.
// ======================================================================
#define FQ 0
#define FK(b) (4096 + (b)*2048)
#define FV(b) (10240 + (b)*2048)
#define FA_SMEM (16384*4)
#define SCL 0.180336877f    // 0.125 * log2(e)
#define NT (Ss/128)         // 16 q-tiles per (b,h)

__global__ void __launch_bounds__(256, 2) flash_tc()
{
    extern __shared__ uint32_t smu[];
    const uint32_t sb = smem_u32(smu);

    const int tid = threadIdx.x;
    const int w = tid >> 5, lane = tid & 31;
    const int gid = lane >> 2, sub = lane & 3;

    const int bh = blockIdx.y;
    const int bb = bh >> 4, h = bh & 15;

    const size_t bho = (size_t)bh * 65536;
    const uint32_t* Kg = g_kp + bho;
    const uint32_t* Vg = g_vp + bho;

#pragma unroll
    for (int t = 0; t < 2; t++) {
        const int qt = t ? (int)blockIdx.x : (NT - 1 - (int)blockIdx.x);
        const int q0 = qt * 128;
        const uint32_t* Qg = g_qp + bho + (size_t)qt * 4096;
        const int nkt = 2 * qt + 2;

        // ---- prolog: Q, then K0/V0, K1/V1 ----
#pragma unroll
        for (int i = 0; i < 4; i++) {
            int f = tid + i * 256;
            cp16(sb + (FQ + f * 4) * 4, Qg + f * 4);
        }
        CP_COMMIT();
#pragma unroll
        for (int i = 0; i < 2; i++) {
            int f = tid + i * 256;
            cp16(sb + (FK(0) + f * 4) * 4, Kg + f * 4);
            cp16(sb + (FV(0) + f * 4) * 4, Vg + f * 4);
        }
        CP_COMMIT();
#pragma unroll
        for (int i = 0; i < 2; i++) {
            int f = tid + i * 256;
            cp16(sb + (FK(1) + f * 4) * 4, Kg + 2048 + f * 4);
            cp16(sb + (FV(1) + f * 4) * 4, Vg + 2048 + f * 4);
        }
        CP_COMMIT();

        CP_WAIT2();          // Q resident
        __syncthreads();

        // Q frags -> regs: 1 m16 x 4 k16 per warp (row block = w)
        uint32_t qf[4][4];
#pragma unroll
        for (int ks = 0; ks < 4; ks++) {
            uint4 av = *((const uint4*)(smu + FQ + (w * 4 + ks) * 128) + lane);
            qf[ks][0] = av.x; qf[ks][1] = av.y;
            qf[ks][2] = av.z; qf[ks][3] = av.w;
        }

        float m_i[2] = {-1e30f, -1e30f};
        float l_i[2] = {0.0f, 0.0f};
        float acc[8][4];
#pragma unroll
        for (int ni = 0; ni < 8; ni++)
#pragma unroll
            for (int cc = 0; cc < 4; cc++) acc[ni][cc] = 0.0f;

        for (int kb = 0; kb < nkt; kb++) {
            const int b = kb % 3;
            const uint32_t* Ks = smu + FK(b);
            const uint32_t* Vs = smu + FV(b);

            if (kb + 1 < nkt) { CP_WAIT1(); } else { CP_WAIT0(); }
            __syncthreads();

            if (kb + 2 < nkt) {
                const int b2 = (kb + 2) % 3;
                const uint32_t* Kn = Kg + (size_t)(kb + 2) * 2048;
                const uint32_t* Vn = Vg + (size_t)(kb + 2) * 2048;
#pragma unroll
                for (int i = 0; i < 2; i++) {
                    int f = tid + i * 256;
                    cp16(sb + (FK(b2) + f * 4) * 4, Kn + f * 4);
                    cp16(sb + (FV(b2) + f * 4) * 4, Vn + f * 4);
                }
                CP_COMMIT();
            }

            // last diagonal tile: warps 0-3 (rows < k0) fully masked
            if (kb == 2 * qt + 1 && w < 4) continue;

            // ---- S = Q K^T (K in B2: one LDS.128 -> two k16 frags) ----
            float s[8][4];
#pragma unroll
            for (int ni = 0; ni < 8; ni++)
#pragma unroll
                for (int cc = 0; cc < 4; cc++) s[ni][cc] = 0.0f;

#pragma unroll
            for (int kp = 0; kp < 2; kp++) {
#pragma unroll
                for (int ni = 0; ni < 8; ni++) {
                    uint4 bv = *((const uint4*)(Ks + (ni * 2 + kp) * 128) + lane);
                    mma16(s[ni], qf[2 * kp],     bv.x, bv.y);
                    mma16(s[ni], qf[2 * kp + 1], bv.z, bv.w);
                }
            }

            // ---- scale + causal mask + online softmax (log2 domain) ----
            const int k0 = kb * 64;
            const bool mt = (kb >= 2 * qt);
            const int r0g = q0 + w * 16 + gid;
            float rmax[2] = {-1e30f, -1e30f};
#pragma unroll
            for (int ni = 0; ni < 8; ni++) {
                int colb = k0 + ni * 8 + 2 * sub;
#pragma unroll
                for (int cc = 0; cc < 4; cc++) {
                    float sv = s[ni][cc] * SCL;
                    if (mt) {
                        int row = r0g + ((cc >> 1) << 3);
                        int col = colb + (cc & 1);
                        if (col > row) sv = -1e30f;
                    }
                    s[ni][cc] = sv;
                    rmax[cc >> 1] = fmaxf(rmax[cc >> 1], sv);
                }
            }
#pragma unroll
            for (int o = 1; o <= 2; o <<= 1) {
                rmax[0] = fmaxf(rmax[0], __shfl_xor_sync(0xffffffffu, rmax[0], o));
                rmax[1] = fmaxf(rmax[1], __shfl_xor_sync(0xffffffffu, rmax[1], o));
            }
            float mnew0 = fmaxf(m_i[0], rmax[0]);
            float mnew1 = fmaxf(m_i[1], rmax[1]);
            float corr0 = exp2f(m_i[0] - mnew0);
            float corr1 = exp2f(m_i[1] - mnew1);
            m_i[0] = mnew0; m_i[1] = mnew1;

            float rsum[2] = {0.0f, 0.0f};
#pragma unroll
            for (int ni = 0; ni < 8; ni++) {
                s[ni][0] = exp2f(s[ni][0] - mnew0);
                s[ni][1] = exp2f(s[ni][1] - mnew0);
                s[ni][2] = exp2f(s[ni][2] - mnew1);
                s[ni][3] = exp2f(s[ni][3] - mnew1);
                rsum[0] += s[ni][0] + s[ni][1];
                rsum[1] += s[ni][2] + s[ni][3];
                acc[ni][0] *= corr0; acc[ni][1] *= corr0;
                acc[ni][2] *= corr1; acc[ni][3] *= corr1;
            }
#pragma unroll
            for (int o = 1; o <= 2; o <<= 1) {
                rsum[0] += __shfl_xor_sync(0xffffffffu, rsum[0], o);
                rsum[1] += __shfl_xor_sync(0xffffffffu, rsum[1], o);
            }
            l_i[0] = l_i[0] * corr0 + rsum[0];
            l_i[1] = l_i[1] * corr1 + rsum[1];

            // P -> A-fragments directly in registers
            uint32_t pa[4][4];
#pragma unroll
            for (int j = 0; j < 4; j++) {
                pa[j][0] = pk(s[2 * j][0],     s[2 * j][1]);
                pa[j][1] = pk(s[2 * j][2],     s[2 * j][3]);
                pa[j][2] = pk(s[2 * j + 1][0], s[2 * j + 1][1]);
                pa[j][3] = pk(s[2 * j + 1][2], s[2 * j + 1][3]);
            }

            // ---- O += P V (V in B2) ----
#pragma unroll
            for (int jp = 0; jp < 2; jp++) {
#pragma unroll
                for (int ni = 0; ni < 8; ni++) {
                    uint4 bv = *((const uint4*)(Vs + (jp * 8 + ni) * 128) + lane);
                    mma16(acc[ni], pa[2 * jp],     bv.x, bv.y);
                    mma16(acc[ni], pa[2 * jp + 1], bv.z, bv.w);
                }
            }
        }

        // ---- normalize, write Op in GLOBAL fp16 A-frag layout ----
        {
            int m16 = bb * 128 + qt * 8 + w;
            float inv0 = 1.0f / l_i[0];
            float inv1 = 1.0f / l_i[1];
#pragma unroll
            for (int j = 0; j < 4; j++) {
                uint4 o = make_uint4(
                    pk(acc[2 * j][0] * inv0,     acc[2 * j][1] * inv0),
                    pk(acc[2 * j][2] * inv1,     acc[2 * j][3] * inv1),
                    pk(acc[2 * j + 1][0] * inv0, acc[2 * j + 1][1] * inv0),
                    pk(acc[2 * j + 1][2] * inv1, acc[2 * j + 1][3] * inv1));
                *(uint4*)(g_op + ((size_t)m16 * (Dd / 16) + h * 4 + j) * 128 + lane * 4) = o;
            }
        }
        __syncthreads();   // smem reuse safe before next tile's prolog
    }
}

// ======================================================================
// Launch
// ======================================================================
extern "C" void kernel_launch(void* const* d_in, const int* in_sizes, int n_in,
                              void* d_out, int out_size)
{
    const float* x  = (const float*)d_in[0];
    const float* wq = (const float*)d_in[1];
    const float* wk = (const float*)d_in[2];
    const float* wv = (const float*)d_in[3];
    const float* wo = (const float*)d_in[4];
    float* out = (float*)d_out;

    cudaFuncSetAttribute(gemm_qkv, cudaFuncAttributeMaxDynamicSharedMemorySize, GEMM_SMEM);
    cudaFuncSetAttribute(gemm_o,   cudaFuncAttributeMaxDynamicSharedMemorySize, GEMM_SMEM);
    cudaFuncSetAttribute(flash_tc, cudaFuncAttributeMaxDynamicSharedMemorySize, FA_SMEM);

    // 0) ONE prep kernel: RoPE tables + all operand permutes
    prep<<<dim3(Mm / 64, Dd / 64, 2), 256>>>(x, wq, wk, wo, wv);

    // 1) fused q/k/v projections + RoPE + frag-permute epilogues
    gemm_qkv<<<dim3(Dd / 128, Mm / 128, 3), 256, GEMM_SMEM>>>();

    // 2) causal flash attention (8-warp CTAs, balanced paired q-tiles)
    flash_tc<<<dim3(NT / 2, Bb * Hh), 256, FA_SMEM>>>();

    // 3) output projection
    gemm_o<<<dim3(Dd / 128, Mm / 128), 256, GEMM_SMEM>>>(out);
}

// round 13
// speedup vs baseline: 1.0775x; 1.0408x over previous
#include <cuda_runtime.h>
#include <cuda_fp16.h>
#include <math.h>
#include <stdint.h>

// Problem constants
#define Bb 2
#define Ss 2048
#define Dd 1024
#define Hh 16
#define HDh 64
#define Mm (Bb*Ss)   // 4096

// Scratch (device globals), all fp16-packed uint32 unless noted
// B2 layout: superblocks (n8, k32) of 128 words; lane l owns l*4+{0..3} =
//   [b0(k16 even), b1(even), b0(k16 odd), b1(odd)]
__device__ uint32_t g_xA[Mm*Dd/2];     // x, A-frag
__device__ uint32_t g_xB[Mm*Dd/2];     // x, B2-frag (n=s)
__device__ uint32_t g_wqB[Dd*Dd/2];    // B2
__device__ uint32_t g_wkB[Dd*Dd/2];    // B2
__device__ uint32_t g_woB[Dd*Dd/2];    // B2
__device__ uint32_t g_wvA[Dd*Dd/2];    // wv, A-frag (for transposed V gemm)
__device__ uint32_t g_qp[Mm*Dd/2];     // Q per (b,h), A-frag
__device__ uint32_t g_kp[Mm*Dd/2];     // K per (b,h), B2 (n=s, k=d)
__device__ uint32_t g_vp[Mm*Dd/2];     // V per (b,h), B2 (k=s, n=d)
__device__ uint32_t g_op[Mm*Dd/2];     // attn out, global A-frag
__device__ float    g_cos[Ss*32];
__device__ float    g_sin[Ss*32];

// ======================================================================
// Helpers
// ======================================================================
__device__ __forceinline__ uint32_t smem_u32(const void* p) {
    uint32_t a;
    asm("{ .reg .u64 t; cvta.to.shared.u64 t, %1; cvt.u32.u64 %0, t; }"
        : "=r"(a) : "l"(p));
    return a;
}
__device__ __forceinline__ uint32_t pk(float a, float b) {
    __half2 h = __floats2half2_rn(a, b);
    return *reinterpret_cast<uint32_t*>(&h);
}
__device__ __forceinline__ void mma16(float* d, const uint32_t* a,
                                      uint32_t b0, uint32_t b1) {
    asm volatile(
        "mma.sync.aligned.m16n8k16.row.col.f32.f16.f16.f32 "
        "{%0,%1,%2,%3}, {%4,%5,%6,%7}, {%8,%9}, {%0,%1,%2,%3};"
        : "+f"(d[0]), "+f"(d[1]), "+f"(d[2]), "+f"(d[3])
        : "r"(a[0]), "r"(a[1]), "r"(a[2]), "r"(a[3]), "r"(b0), "r"(b1));
}
__device__ __forceinline__ void cp16(uint32_t dst, const void* src) {
    asm volatile("cp.async.cg.shared.global [%0], [%1], 16;"
                 :: "r"(dst), "l"(src) : "memory");
}
#define CP_COMMIT() asm volatile("cp.async.commit_group;" ::: "memory")
#define CP_WAIT0()  asm volatile("cp.async.wait_group 0;" ::: "memory")
#define CP_WAIT1()  asm volatile("cp.async.wait_group 1;" ::: "memory")
#define CP_WAIT2()  asm volatile("cp.async.wait_group 2;" ::: "memory")

// ======================================================================
// prep: ONE kernel for RoPE tables + all operand permutes.
// z=0: x -> xA (A-frag) + xB (B2) + a 64-entry table slice per CTA.
// z=1: bx>>4 selects {wq,wk,wo,wv}; first three -> B2, wv -> A-frag.
// ======================================================================
__global__ __launch_bounds__(256) void prep(
    const float* __restrict__ x,
    const float* __restrict__ wq, const float* __restrict__ wk,
    const float* __restrict__ wo, const float* __restrict__ wv)
{
    __shared__ float ts[64][68];
    const int tid = threadIdx.x;
    const int w = tid >> 5, l = tid & 31;
    const int gid = l >> 2, sub = l & 3;

    if (blockIdx.z == 0) {
        if (tid < 64) {
            int idx = (int)(blockIdx.x * 16 + blockIdx.y) * 64 + tid;
            int s = idx >> 5, i = idx & 31;
            double inv = pow(10000.0, -((double)(2 * i)) / (double)HDh);
            double sd, cd;
            sincos((double)s * inv, &sd, &cd);
            g_cos[idx] = (float)cd;
            g_sin[idx] = (float)sd;
        }
        const int r0 = blockIdx.x * 64, c0 = blockIdx.y * 64;
#pragma unroll
        for (int i = 0; i < 4; i++) {
            int f = tid + i * 256;
            int r = f >> 4, c4 = (f & 15) << 2;
            *(float4*)&ts[r][c4] = *(const float4*)(x + (size_t)(r0 + r) * Dd + c0 + c4);
        }
        __syncthreads();
        {
            int mi = w >> 1;
#pragma unroll
            for (int jj = 0; jj < 2; jj++) {
                int j = (w & 1) * 2 + jj;
                int r = mi * 16 + gid, d = j * 16 + 2 * sub;
                uint4 o = make_uint4(
                    pk(ts[r][d],         ts[r][d + 1]),
                    pk(ts[r + 8][d],     ts[r + 8][d + 1]),
                    pk(ts[r][d + 8],     ts[r][d + 9]),
                    pk(ts[r + 8][d + 8], ts[r + 8][d + 9]));
                *(uint4*)(g_xA + ((size_t)(r0 / 16 + mi) * (Dd / 16) + (c0 / 16 + j)) * 128 + l * 4) = o;
            }
        }
        {
            int n = w * 8 + gid;
#pragma unroll
            for (int kp = 0; kp < 2; kp++) {
                int d0 = kp * 32 + 2 * sub;
                uint4 o = make_uint4(
                    pk(ts[n][d0],      ts[n][d0 + 1]),
                    pk(ts[n][d0 + 8],  ts[n][d0 + 9]),
                    pk(ts[n][d0 + 16], ts[n][d0 + 17]),
                    pk(ts[n][d0 + 24], ts[n][d0 + 25]));
                *(uint4*)(g_xB + ((size_t)(r0 / 8 + w) * (Dd / 32) + (c0 / 32 + kp)) * 128 + l * 4) = o;
            }
        }
        return;
    }

    const int wsel = blockIdx.x >> 4;
    const float* W = (wsel == 0) ? wq : (wsel == 1) ? wk : (wsel == 2) ? wo : wv;
    const int n0 = (blockIdx.x & 15) * 64, k0 = blockIdx.y * 64;
#pragma unroll
    for (int i = 0; i < 4; i++) {
        int f = tid + i * 256;
        int r = f >> 4, c4 = (f & 15) << 2;
        *(float4*)&ts[r][c4] = *(const float4*)(W + (size_t)(n0 + r) * Dd + k0 + c4);
    }
    __syncthreads();

    if (wsel == 3) {
        int mi = w >> 1;
#pragma unroll
        for (int jj = 0; jj < 2; jj++) {
            int j = (w & 1) * 2 + jj;
            int r = mi * 16 + gid, d = j * 16 + 2 * sub;
            uint4 o = make_uint4(
                pk(ts[r][d],         ts[r][d + 1]),
                pk(ts[r + 8][d],     ts[r + 8][d + 1]),
                pk(ts[r][d + 8],     ts[r][d + 9]),
                pk(ts[r + 8][d + 8], ts[r + 8][d + 9]));
            *(uint4*)(g_wvA + ((size_t)(n0 / 16 + mi) * (Dd / 16) + (k0 / 16 + j)) * 128 + l * 4) = o;
        }
        return;
    }
    uint32_t* D = (wsel == 0) ? g_wqB : (wsel == 1) ? g_wkB : g_woB;
    int n = w * 8 + gid;
#pragma unroll
    for (int kp = 0; kp < 2; kp++) {
        int d0 = kp * 32 + 2 * sub;
        uint4 o = make_uint4(
            pk(ts[n][d0],      ts[n][d0 + 1]),
            pk(ts[n][d0 + 8],  ts[n][d0 + 9]),
            pk(ts[n][d0 + 16], ts[n][d0 + 17]),
            pk(ts[n][d0 + 24], ts[n][d0 + 25]));
        *(uint4*)(D + ((size_t)(n0 / 8 + w) * (Dd / 32) + (k0 / 32 + kp)) * 128 + l * 4) = o;
    }
}

// ======================================================================
// GEMM mainloop: CTA 128x128, 128 thr, 4 warps of 64x64 (2x2 grid).
// Doubles FLOP/smem-byte vs 32x64 tiles -> crossbar no longer binding.
// A in A-frag, B in B2. 16 chunks of 64 k, 3-stage cp.async.
// smem: A[3][4096] | B[3][4096] words = 96 KB -> 2 CTA/SM.
// ======================================================================
#define GEMM_SMEM 98304

__device__ __forceinline__ void gemm_main(
    const uint32_t* __restrict__ Ab, const uint32_t* __restrict__ Bp,
    uint32_t* smu, float acc[4][8][4])
{
    const uint32_t sb = smem_u32(smu);
    const int tid = threadIdx.x;
    const int w = tid >> 5, lane = tid & 31;
    const int wm = w >> 1, wn = w & 1;

    const uint32_t* srca[8];
    const uint32_t* srcw[8];
#pragma unroll
    for (int i = 0; i < 8; i++) {
        int f = tid + i * 128;
        int ba = f >> 5, wa = f & 31;
        srca[i] = Ab + ((size_t)(ba >> 2) * (Dd / 16) + (ba & 3)) * 128 + wa * 4;
        int bw = f >> 5, wb = f & 31;
        srcw[i] = Bp + ((size_t)(bw >> 1) * (Dd / 32) + (bw & 1)) * 128 + wb * 4;
    }
#pragma unroll
    for (int mi = 0; mi < 4; mi++)
#pragma unroll
        for (int ni = 0; ni < 8; ni++)
#pragma unroll
            for (int cc = 0; cc < 4; cc++) acc[mi][ni][cc] = 0.0f;

#define GISSUE(c) do { int _b = (c) % 3; \
    _Pragma("unroll") \
    for (int i = 0; i < 8; i++) { int f = tid + i * 128; \
        cp16(sb + (_b * 4096 + f * 4) * 4, srca[i] + (size_t)(c) * 512); \
        cp16(sb + (12288 + _b * 4096 + f * 4) * 4, srcw[i] + (size_t)(c) * 256); } \
    CP_COMMIT(); } while (0)

    GISSUE(0);
    GISSUE(1);
    for (int c = 0; c < 16; c++) {
        if (c + 1 < 16) { CP_WAIT1(); } else { CP_WAIT0(); }
        __syncthreads();
        if (c + 2 < 16) GISSUE(c + 2);
        const uint32_t* As = smu + (c % 3) * 4096;
        const uint32_t* Ws = smu + 12288 + (c % 3) * 4096;
#pragma unroll
        for (int kp = 0; kp < 2; kp++) {
            uint32_t a[4][2][4];
#pragma unroll
            for (int mi = 0; mi < 4; mi++)
#pragma unroll
                for (int kk = 0; kk < 2; kk++) {
                    uint4 av = *((const uint4*)(As + ((wm * 4 + mi) * 4 + kp * 2 + kk) * 128) + lane);
                    a[mi][kk][0] = av.x; a[mi][kk][1] = av.y;
                    a[mi][kk][2] = av.z; a[mi][kk][3] = av.w;
                }
#pragma unroll
            for (int ni = 0; ni < 8; ni++) {
                uint4 bv = *((const uint4*)(Ws + ((wn * 8 + ni) * 2 + kp) * 128) + lane);
#pragma unroll
                for (int mi = 0; mi < 4; mi++) {
                    mma16(acc[mi][ni], a[mi][0], bv.x, bv.y);
                    mma16(acc[mi][ni], a[mi][1], bv.z, bv.w);
                }
            }
        }
    }
#undef GISSUE
}

// ======================================================================
// Fused qkv projections. z=0: Q + RoPE -> Qp (A-frag per bh).
// z=1: K + RoPE -> Kp (B2). z=2: V transposed -> Vp (B2, k=s, n=d).
// Warp = 64 rows x one 64-col head.
// ======================================================================
__global__ void __launch_bounds__(128, 2) gemm_qkv()
{
    extern __shared__ uint32_t smu[];
    const int z = blockIdx.z;
    int row0, col0;
    const uint32_t *Ab, *Bp;
    if (z == 2) {
        row0 = blockIdx.x * 128;                 // over Dd (V out-dim)
        col0 = blockIdx.y * 128;                 // over Mm (s)
        Ab = g_wvA + (size_t)(row0 >> 4) * (Dd / 16) * 128;
        Bp = g_xB  + (size_t)(col0 >> 3) * (Dd / 32) * 128;
    } else {
        row0 = blockIdx.y * 128;                 // over Mm (s)
        col0 = blockIdx.x * 128;                 // over Dd
        Ab = g_xA + (size_t)(row0 >> 4) * (Dd / 16) * 128;
        Bp = ((z == 0) ? g_wqB : g_wkB) + (size_t)(col0 >> 3) * (Dd / 32) * 128;
    }

    float acc[4][8][4];
    gemm_main(Ab, Bp, smu, acc);

    const int tid = threadIdx.x;
    const int w = tid >> 5, lane = tid & 31;
    const int gid = lane >> 2, sub = lane & 3;
    const int wm = w >> 1, wn = w & 1;

    if (z == 2) {
        // Vp (B2): warp covers d = dW..dW+63 (one head), s = sB..sB+63
        const int bb = col0 >> 11;
        const int sB = (col0 & 2047) + wn * 64;
        const int dW = row0 + wm * 64;
        const int bh = bb * 16 + (dW >> 6);
        uint32_t* dst = g_vp + (size_t)bh * 65536;
#pragma unroll
        for (int d8 = 0; d8 < 8; d8++) {
            int mi = d8 >> 1, hh = d8 & 1;
#pragma unroll
            for (int sp = 0; sp < 2; sp++) {
                uint4 o = make_uint4(
                    pk(acc[mi][4 * sp][2 * hh],     acc[mi][4 * sp][2 * hh + 1]),
                    pk(acc[mi][4 * sp + 1][2 * hh], acc[mi][4 * sp + 1][2 * hh + 1]),
                    pk(acc[mi][4 * sp + 2][2 * hh], acc[mi][4 * sp + 2][2 * hh + 1]),
                    pk(acc[mi][4 * sp + 3][2 * hh], acc[mi][4 * sp + 3][2 * hh + 1]));
                *(uint4*)(dst + (((size_t)(sB >> 5) + sp) * 8 + d8) * 128 + lane * 4) = o;
            }
        }
        return;
    }

    // z 0/1: RoPE in registers (pair d, d+32 = acc[..][ni], acc[..][ni+4])
    const int bb = row0 >> 11;
    const int sB = (row0 & 2047) + wm * 64;
    const int bh = bb * 16 + (col0 >> 6) + wn;
#pragma unroll
    for (int mi = 0; mi < 4; mi++) {
#pragma unroll
        for (int hh = 0; hh < 2; hh++) {
            int s = sB + mi * 16 + gid + 8 * hh;
#pragma unroll
            for (int ni = 0; ni < 4; ni++) {
                float2 c2 = *(const float2*)&g_cos[s * 32 + ni * 8 + 2 * sub];
                float2 s2 = *(const float2*)&g_sin[s * 32 + ni * 8 + 2 * sub];
                {
                    int cc = 2 * hh;
                    float x1 = acc[mi][ni][cc], x2 = acc[mi][ni + 4][cc];
                    acc[mi][ni][cc]     = x1 * c2.x - x2 * s2.x;
                    acc[mi][ni + 4][cc] = x2 * c2.x + x1 * s2.x;
                }
                {
                    int cc = 2 * hh + 1;
                    float x1 = acc[mi][ni][cc], x2 = acc[mi][ni + 4][cc];
                    acc[mi][ni][cc]     = x1 * c2.y - x2 * s2.y;
                    acc[mi][ni + 4][cc] = x2 * c2.y + x1 * s2.y;
                }
            }
        }
    }

    if (z == 0) {
        uint32_t* dst = g_qp + (size_t)bh * 65536;
#pragma unroll
        for (int mi = 0; mi < 4; mi++) {
#pragma unroll
            for (int j = 0; j < 4; j++) {
                uint4 o = make_uint4(
                    pk(acc[mi][2 * j][0],     acc[mi][2 * j][1]),
                    pk(acc[mi][2 * j][2],     acc[mi][2 * j][3]),
                    pk(acc[mi][2 * j + 1][0], acc[mi][2 * j + 1][1]),
                    pk(acc[mi][2 * j + 1][2], acc[mi][2 * j + 1][3]));
                *(uint4*)(dst + ((size_t)((sB >> 4) + mi) * 4 + j) * 128 + lane * 4) = o;
            }
        }
    } else {
        uint32_t* dst = g_kp + (size_t)bh * 65536;
#pragma unroll
        for (int s8 = 0; s8 < 8; s8++) {
            int mi = s8 >> 1, hh = s8 & 1;
#pragma unroll
            for (int jp = 0; jp < 2; jp++) {
                uint4 o = make_uint4(
                    pk(acc[mi][4 * jp][2 * hh],     acc[mi][4 * jp][2 * hh + 1]),
                    pk(acc[mi][4 * jp + 1][2 * hh], acc[mi][4 * jp + 1][2 * hh + 1]),
                    pk(acc[mi][4 * jp + 2][2 * hh], acc[mi][4 * jp + 2][2 * hh + 1]),
                    pk(acc[mi][4 * jp + 3][2 * hh], acc[mi][4 * jp + 3][2 * hh + 1]));
                *(uint4*)(dst + (((size_t)((sB >> 3) + s8)) * 2 + jp) * 128 + lane * 4) = o;
            }
        }
    }
}

// ======================================================================
// Output projection: out = Op @ wo^T (fp32 row-major result)
// ======================================================================
__global__ void __launch_bounds__(128, 2) gemm_o(float* __restrict__ C)
{
    extern __shared__ uint32_t smu[];
    const int row0 = blockIdx.y * 128, col0 = blockIdx.x * 128;
    const uint32_t* Ab = g_op  + (size_t)(row0 >> 4) * (Dd / 16) * 128;
    const uint32_t* Bp = g_woB + (size_t)(col0 >> 3) * (Dd / 32) * 128;

    float acc[4][8][4];
    gemm_main(Ab, Bp, smu, acc);

    const int tid = threadIdx.x;
    const int w = tid >> 5, lane = tid & 31;
    const int gid = lane >> 2, sub = lane & 3;
    const int wm = w >> 1, wn = w & 1;
#pragma unroll
    for (int mi = 0; mi < 4; mi++) {
        int row = row0 + wm * 64 + mi * 16 + gid;
#pragma unroll
        for (int ni = 0; ni < 8; ni++) {
            int col = col0 + wn * 64 + ni * 8 + 2 * sub;
            *(float2*)(C + (size_t)row * Dd + col) =
                make_float2(acc[mi][ni][0], acc[mi][ni][1]);
            *(float2*)(C + (size_t)(row + 8) * Dd + col) =
                make_float2(acc[mi][ni][2], acc[mi][ni][3]);
        }
    }
}

// ======================================================================
// Flash attention, causal, fp16 m16n8k16, B2-frag K/V (unchanged R12).
// 8 warps (256 thr), each warp 16 q-rows x 64 cols; 2 CTA/SM.
// PAIRED q-tiles {NT-1-bx, bx}: constant 34 iterations per CTA.
// ======================================================================
#define FQ 0
#define FK(b) (4096 + (b)*2048)
#define FV(b) (10240 + (b)*2048)
#define FA_SMEM (16384*4)
#define SCL 0.180336877f    // 0.125 * log2(e)
#define NT (Ss/128)         // 16 q-tiles per (b,h)

__global__ void __launch_bounds__(256, 2) flash_tc()
{
    extern __shared__ uint32_t smu[];
    const uint32_t sb = smem_u32(smu);

    const int tid = threadIdx.x;
    const int w = tid >> 5, lane = tid & 31;
    const int gid = lane >> 2, sub = lane & 3;

    const int bh = blockIdx.y;
    const int bb = bh >> 4, h = bh & 15;

    const size_t bho = (size_t)bh * 65536;
    const uint32_t* Kg = g_kp + bho;
    const uint32_t* Vg = g_vp + bho;

#pragma unroll
    for (int t = 0; t < 2; t++) {
        const int qt = t ? (int)blockIdx.x : (NT - 1 - (int)blockIdx.x);
        const int q0 = qt * 128;
        const uint32_t* Qg = g_qp + bho + (size_t)qt * 4096;
        const int nkt = 2 * qt + 2;

#pragma unroll
        for (int i = 0; i < 4; i++) {
            int f = tid + i * 256;
            cp16(sb + (FQ + f * 4) * 4, Qg + f * 4);
        }
        CP_COMMIT();
#pragma unroll
        for (int i = 0; i < 2; i++) {
            int f = tid + i * 256;
            cp16(sb + (FK(0) + f * 4) * 4, Kg + f * 4);
            cp16(sb + (FV(0) + f * 4) * 4, Vg + f * 4);
        }
        CP_COMMIT();
#pragma unroll
        for (int i = 0; i < 2; i++) {
            int f = tid + i * 256;
            cp16(sb + (FK(1) + f * 4) * 4, Kg + 2048 + f * 4);
            cp16(sb + (FV(1) + f * 4) * 4, Vg + 2048 + f * 4);
        }
        CP_COMMIT();

        CP_WAIT2();
        __syncthreads();

        uint32_t qf[4][4];
#pragma unroll
        for (int ks = 0; ks < 4; ks++) {
            uint4 av = *((const uint4*)(smu + FQ + (w * 4 + ks) * 128) + lane);
            qf[ks][0] = av.x; qf[ks][1] = av.y;
            qf[ks][2] = av.z; qf[ks][3] = av.w;
        }

        float m_i[2] = {-1e30f, -1e30f};
        float l_i[2] = {0.0f, 0.0f};
        float acc[8][4];
#pragma unroll
        for (int ni = 0; ni < 8; ni++)
#pragma unroll
            for (int cc = 0; cc < 4; cc++) acc[ni][cc] = 0.0f;

        for (int kb = 0; kb < nkt; kb++) {
            const int b = kb % 3;
            const uint32_t* Ks = smu + FK(b);
            const uint32_t* Vs = smu + FV(b);

            if (kb + 1 < nkt) { CP_WAIT1(); } else { CP_WAIT0(); }
            __syncthreads();

            if (kb + 2 < nkt) {
                const int b2 = (kb + 2) % 3;
                const uint32_t* Kn = Kg + (size_t)(kb + 2) * 2048;
                const uint32_t* Vn = Vg + (size_t)(kb + 2) * 2048;
#pragma unroll
                for (int i = 0; i < 2; i++) {
                    int f = tid + i * 256;
                    cp16(sb + (FK(b2) + f * 4) * 4, Kn + f * 4);
                    cp16(sb + (FV(b2) + f * 4) * 4, Vn + f * 4);
                }
                CP_COMMIT();
            }

            if (kb == 2 * qt + 1 && w < 4) continue;

            float s[8][4];
#pragma unroll
            for (int ni = 0; ni < 8; ni++)
#pragma unroll
                for (int cc = 0; cc < 4; cc++) s[ni][cc] = 0.0f;

#pragma unroll
            for (int kp = 0; kp < 2; kp++) {
#pragma unroll
                for (int ni = 0; ni < 8; ni++) {
                    uint4 bv = *((const uint4*)(Ks + (ni * 2 + kp) * 128) + lane);
                    mma16(s[ni], qf[2 * kp],     bv.x, bv.y);
                    mma16(s[ni], qf[2 * kp + 1], bv.z, bv.w);
                }
            }

            const int k0 = kb * 64;
            const bool mt = (kb >= 2 * qt);
            const int r0g = q0 + w * 16 + gid;
            float rmax[2] = {-1e30f, -1e30f};
#pragma unroll
            for (int ni = 0; ni < 8; ni++) {
                int colb = k0 + ni * 8 + 2 * sub;
#pragma unroll
                for (int cc = 0; cc < 4; cc++) {
                    float sv = s[ni][cc] * SCL;
                    if (mt) {
                        int row = r0g + ((cc >> 1) << 3);
                        int col = colb + (cc & 1);
                        if (col > row) sv = -1e30f;
                    }
                    s[ni][cc] = sv;
                    rmax[cc >> 1] = fmaxf(rmax[cc >> 1], sv);
                }
            }
#pragma unroll
            for (int o = 1; o <= 2; o <<= 1) {
                rmax[0] = fmaxf(rmax[0], __shfl_xor_sync(0xffffffffu, rmax[0], o));
                rmax[1] = fmaxf(rmax[1], __shfl_xor_sync(0xffffffffu, rmax[1], o));
            }
            float mnew0 = fmaxf(m_i[0], rmax[0]);
            float mnew1 = fmaxf(m_i[1], rmax[1]);
            float corr0 = exp2f(m_i[0] - mnew0);
            float corr1 = exp2f(m_i[1] - mnew1);
            m_i[0] = mnew0; m_i[1] = mnew1;

            float rsum[2] = {0.0f, 0.0f};
#pragma unroll
            for (int ni = 0; ni < 8; ni++) {
                s[ni][0] = exp2f(s[ni][0] - mnew0);
                s[ni][1] = exp2f(s[ni][1] - mnew0);
                s[ni][2] = exp2f(s[ni][2] - mnew1);
                s[ni][3] = exp2f(s[ni][3] - mnew1);
                rsum[0] += s[ni][0] + s[ni][1];
                rsum[1] += s[ni][2] + s[ni][3];
                acc[ni][0] *= corr0; acc[ni][1] *= corr0;
                acc[ni][2] *= corr1; acc[ni][3] *= corr1;
            }
#pragma unroll
            for (int o = 1; o <= 2; o <<= 1) {
                rsum[0] += __shfl_xor_sync(0xffffffffu, rsum[0], o);
                rsum[1] += __shfl_xor_sync(0xffffffffu, rsum[1], o);
            }
            l_i[0] = l_i[0] * corr0 + rsum[0];
            l_i[1] = l_i[1] * corr1 + rsum[1];

            uint32_t pa[4][4];
#pragma unroll
            for (int j = 0; j < 4; j++) {
                pa[j][0] = pk(s[2 * j][0],     s[2 * j][1]);
                pa[j][1] = pk(s[2 * j][2],     s[2 * j][3]);
                pa[j][2] = pk(s[2 * j + 1][0], s[2 * j + 1][1]);
                pa[j][3] = pk(s[2 * j + 1][2], s[2 * j + 1][3]);
            }

#pragma unroll
            for (int jp = 0; jp < 2; jp++) {
#pragma unroll
                for (int ni = 0; ni < 8; ni++) {
                    uint4 bv = *((const uint4*)(Vs + (jp * 8 + ni) * 128) + lane);
                    mma16(acc[ni], pa[2 * jp],     bv.x, bv.y);
                    mma16(acc[ni], pa[2 * jp + 1], bv.z, bv.w);
                }
            }
        }

        {
            int m16 = bb * 128 + qt * 8 + w;
            float inv0 = 1.0f / l_i[0];
            float inv1 = 1.0f / l_i[1];
#pragma unroll
            for (int j = 0; j < 4; j++) {
                uint4 o = make_uint4(
                    pk(acc[2 * j][0] * inv0,     acc[2 * j][1] * inv0),
                    pk(acc[2 * j][2] * inv1,     acc[2 * j][3] * inv1),
                    pk(acc[2 * j + 1][0] * inv0, acc[2 * j + 1][1] * inv0),
                    pk(acc[2 * j + 1][2] * inv1, acc[2 * j + 1][3] * inv1));
                *(uint4*)(g_op + ((size_t)m16 * (Dd / 16) + h * 4 + j) * 128 + lane * 4) = o;
            }
        }
        __syncthreads();
    }
}

// ======================================================================
// Launch
// ======================================================================
extern "C" void kernel_launch(void* const* d_in, const int* in_sizes, int n_in,
                              void* d_out, int out_size)
{
    const float* x  = (const float*)d_in[0];
    const float* wq = (const float*)d_in[1];
    const float* wk = (const float*)d_in[2];
    const float* wv = (const float*)d_in[3];
    const float* wo = (const float*)d_in[4];
    float* out = (float*)d_out;

    cudaFuncSetAttribute(gemm_qkv, cudaFuncAttributeMaxDynamicSharedMemorySize, GEMM_SMEM);
    cudaFuncSetAttribute(gemm_o,   cudaFuncAttributeMaxDynamicSharedMemorySize, GEMM_SMEM);
    cudaFuncSetAttribute(flash_tc, cudaFuncAttributeMaxDynamicSharedMemorySize, FA_SMEM);

    // 0) ONE prep kernel: RoPE tables + all operand permutes
    prep<<<dim3(Mm / 64, Dd / 64, 2), 256>>>(x, wq, wk, wo, wv);

    // 1) fused q/k/v projections + RoPE + frag-permute epilogues
    gemm_qkv<<<dim3(Dd / 128, Mm / 128, 3), 128, GEMM_SMEM>>>();

    // 2) causal flash attention (8-warp CTAs, balanced paired q-tiles)
    flash_tc<<<dim3(NT / 2, Bb * Hh), 256, FA_SMEM>>>();

    // 3) output projection
    gemm_o<<<dim3(Dd / 128, Mm / 128), 128, GEMM_SMEM>>>(out);
}

// round 14
// speedup vs baseline: 1.0812x; 1.0034x over previous
#include <cuda_runtime.h>
#include <cuda_fp16.h>
#include <math.h>
#include <stdint.h>

// Problem constants
#define Bb 2
#define Ss 2048
#define Dd 1024
#define Hh 16
#define HDh 64
#define Mm (Bb*Ss)   // 4096

// Scratch (device globals), all fp16-packed uint32 unless noted
// B2 layout: superblocks (n8, k32) of 128 words; lane l owns l*4+{0..3} =
//   [b0(k16 even), b1(even), b0(k16 odd), b1(odd)]
__device__ uint32_t g_xA[Mm*Dd/2];     // x, A-frag
__device__ uint32_t g_xB[Mm*Dd/2];     // x, B2-frag (n=s)
__device__ uint32_t g_wqB[Dd*Dd/2];    // B2
__device__ uint32_t g_wkB[Dd*Dd/2];    // B2
__device__ uint32_t g_woB[Dd*Dd/2];    // B2
__device__ uint32_t g_wvA[Dd*Dd/2];    // wv, A-frag (for transposed V gemm)
__device__ uint32_t g_qp[Mm*Dd/2];     // Q per (b,h), A-frag
__device__ uint32_t g_kp[Mm*Dd/2];     // K per (b,h), B2 (n=s, k=d)
__device__ uint32_t g_vp[Mm*Dd/2];     // V per (b,h), B2 (k=s, n=d)
__device__ uint32_t g_op[Mm*Dd/2];     // attn out, global A-frag
__device__ float    g_cos[Ss*32];
__device__ float    g_sin[Ss*32];

// ======================================================================
// Helpers
// ======================================================================
__device__ __forceinline__ uint32_t smem_u32(const void* p) {
    uint32_t a;
    asm("{ .reg .u64 t; cvta.to.shared.u64 t, %1; cvt.u32.u64 %0, t; }"
        : "=r"(a) : "l"(p));
    return a;
}
__device__ __forceinline__ uint32_t pk(float a, float b) {
    __half2 h = __floats2half2_rn(a, b);
    return *reinterpret_cast<uint32_t*>(&h);
}
// 2^x on two fp16 lanes in one MUFU op
__device__ __forceinline__ uint32_t h2exp2(uint32_t h) {
    uint32_t e;
    asm("ex2.approx.f16x2 %0, %1;" : "=r"(e) : "r"(h));
    return e;
}
__device__ __forceinline__ float2 h2f2(uint32_t h) {
    __half2 v = *reinterpret_cast<__half2*>(&h);
    return __half22float2(v);
}
__device__ __forceinline__ void mma16(float* d, const uint32_t* a,
                                      uint32_t b0, uint32_t b1) {
    asm volatile(
        "mma.sync.aligned.m16n8k16.row.col.f32.f16.f16.f32 "
        "{%0,%1,%2,%3}, {%4,%5,%6,%7}, {%8,%9}, {%0,%1,%2,%3};"
        : "+f"(d[0]), "+f"(d[1]), "+f"(d[2]), "+f"(d[3])
        : "r"(a[0]), "r"(a[1]), "r"(a[2]), "r"(a[3]), "r"(b0), "r"(b1));
}
__device__ __forceinline__ void cp16(uint32_t dst, const void* src) {
    asm volatile("cp.async.cg.shared.global [%0], [%1], 16;"
                 :: "r"(dst), "l"(src) : "memory");
}
#define CP_COMMIT() asm volatile("cp.async.commit_group;" ::: "memory")
#define CP_WAIT0()  asm volatile("cp.async.wait_group 0;" ::: "memory")
#define CP_WAIT1()  asm volatile("cp.async.wait_group 1;" ::: "memory")
#define CP_WAIT2()  asm volatile("cp.async.wait_group 2;" ::: "memory")

// ======================================================================
// prep: ONE kernel for RoPE tables + all operand permutes.
// ======================================================================
__global__ __launch_bounds__(256) void prep(
    const float* __restrict__ x,
    const float* __restrict__ wq, const float* __restrict__ wk,
    const float* __restrict__ wo, const float* __restrict__ wv)
{
    __shared__ float ts[64][68];
    const int tid = threadIdx.x;
    const int w = tid >> 5, l = tid & 31;
    const int gid = l >> 2, sub = l & 3;

    if (blockIdx.z == 0) {
        if (tid < 64) {
            int idx = (int)(blockIdx.x * 16 + blockIdx.y) * 64 + tid;
            int s = idx >> 5, i = idx & 31;
            double inv = pow(10000.0, -((double)(2 * i)) / (double)HDh);
            double sd, cd;
            sincos((double)s * inv, &sd, &cd);
            g_cos[idx] = (float)cd;
            g_sin[idx] = (float)sd;
        }
        const int r0 = blockIdx.x * 64, c0 = blockIdx.y * 64;
#pragma unroll
        for (int i = 0; i < 4; i++) {
            int f = tid + i * 256;
            int r = f >> 4, c4 = (f & 15) << 2;
            *(float4*)&ts[r][c4] = *(const float4*)(x + (size_t)(r0 + r) * Dd + c0 + c4);
        }
        __syncthreads();
        {
            int mi = w >> 1;
#pragma unroll
            for (int jj = 0; jj < 2; jj++) {
                int j = (w & 1) * 2 + jj;
                int r = mi * 16 + gid, d = j * 16 + 2 * sub;
                uint4 o = make_uint4(
                    pk(ts[r][d],         ts[r][d + 1]),
                    pk(ts[r + 8][d],     ts[r + 8][d + 1]),
                    pk(ts[r][d + 8],     ts[r][d + 9]),
                    pk(ts[r + 8][d + 8], ts[r + 8][d + 9]));
                *(uint4*)(g_xA + ((size_t)(r0 / 16 + mi) * (Dd / 16) + (c0 / 16 + j)) * 128 + l * 4) = o;
            }
        }
        {
            int n = w * 8 + gid;
#pragma unroll
            for (int kp = 0; kp < 2; kp++) {
                int d0 = kp * 32 + 2 * sub;
                uint4 o = make_uint4(
                    pk(ts[n][d0],      ts[n][d0 + 1]),
                    pk(ts[n][d0 + 8],  ts[n][d0 + 9]),
                    pk(ts[n][d0 + 16], ts[n][d0 + 17]),
                    pk(ts[n][d0 + 24], ts[n][d0 + 25]));
                *(uint4*)(g_xB + ((size_t)(r0 / 8 + w) * (Dd / 32) + (c0 / 32 + kp)) * 128 + l * 4) = o;
            }
        }
        return;
    }

    const int wsel = blockIdx.x >> 4;
    const float* W = (wsel == 0) ? wq : (wsel == 1) ? wk : (wsel == 2) ? wo : wv;
    const int n0 = (blockIdx.x & 15) * 64, k0 = blockIdx.y * 64;
#pragma unroll
    for (int i = 0; i < 4; i++) {
        int f = tid + i * 256;
        int r = f >> 4, c4 = (f & 15) << 2;
        *(float4*)&ts[r][c4] = *(const float4*)(W + (size_t)(n0 + r) * Dd + k0 + c4);
    }
    __syncthreads();

    if (wsel == 3) {
        int mi = w >> 1;
#pragma unroll
        for (int jj = 0; jj < 2; jj++) {
            int j = (w & 1) * 2 + jj;
            int r = mi * 16 + gid, d = j * 16 + 2 * sub;
            uint4 o = make_uint4(
                pk(ts[r][d],         ts[r][d + 1]),
                pk(ts[r + 8][d],     ts[r + 8][d + 1]),
                pk(ts[r][d + 8],     ts[r][d + 9]),
                pk(ts[r + 8][d + 8], ts[r + 8][d + 9]));
            *(uint4*)(g_wvA + ((size_t)(n0 / 16 + mi) * (Dd / 16) + (k0 / 16 + j)) * 128 + l * 4) = o;
        }
        return;
    }
    uint32_t* D = (wsel == 0) ? g_wqB : (wsel == 1) ? g_wkB : g_woB;
    int n = w * 8 + gid;
#pragma unroll
    for (int kp = 0; kp < 2; kp++) {
        int d0 = kp * 32 + 2 * sub;
        uint4 o = make_uint4(
            pk(ts[n][d0],      ts[n][d0 + 1]),
            pk(ts[n][d0 + 8],  ts[n][d0 + 9]),
            pk(ts[n][d0 + 16], ts[n][d0 + 17]),
            pk(ts[n][d0 + 24], ts[n][d0 + 25]));
        *(uint4*)(D + ((size_t)(n0 / 8 + w) * (Dd / 32) + (k0 / 32 + kp)) * 128 + l * 4) = o;
    }
}

// ======================================================================
// GEMM mainloop: CTA 128x128, 128 thr, 4 warps of 64x64 (2x2 grid).
// A in A-frag, B in B2. 16 chunks of 64 k, 3-stage cp.async.
// smem: A[3][4096] | B[3][4096] words = 96 KB -> 2 CTA/SM.
// ======================================================================
#define GEMM_SMEM 98304

__device__ __forceinline__ void gemm_main(
    const uint32_t* __restrict__ Ab, const uint32_t* __restrict__ Bp,
    uint32_t* smu, float acc[4][8][4])
{
    const uint32_t sb = smem_u32(smu);
    const int tid = threadIdx.x;
    const int w = tid >> 5, lane = tid & 31;
    const int wm = w >> 1, wn = w & 1;

    const uint32_t* srca[8];
    const uint32_t* srcw[8];
#pragma unroll
    for (int i = 0; i < 8; i++) {
        int f = tid + i * 128;
        int ba = f >> 5, wa = f & 31;
        srca[i] = Ab + ((size_t)(ba >> 2) * (Dd / 16) + (ba & 3)) * 128 + wa * 4;
        int bw = f >> 5, wb = f & 31;
        srcw[i] = Bp + ((size_t)(bw >> 1) * (Dd / 32) + (bw & 1)) * 128 + wb * 4;
    }
#pragma unroll
    for (int mi = 0; mi < 4; mi++)
#pragma unroll
        for (int ni = 0; ni < 8; ni++)
#pragma unroll
            for (int cc = 0; cc < 4; cc++) acc[mi][ni][cc] = 0.0f;

#define GISSUE(c) do { int _b = (c) % 3; \
    _Pragma("unroll") \
    for (int i = 0; i < 8; i++) { int f = tid + i * 128; \
        cp16(sb + (_b * 4096 + f * 4) * 4, srca[i] + (size_t)(c) * 512); \
        cp16(sb + (12288 + _b * 4096 + f * 4) * 4, srcw[i] + (size_t)(c) * 256); } \
    CP_COMMIT(); } while (0)

    GISSUE(0);
    GISSUE(1);
    for (int c = 0; c < 16; c++) {
        if (c + 1 < 16) { CP_WAIT1(); } else { CP_WAIT0(); }
        __syncthreads();
        if (c + 2 < 16) GISSUE(c + 2);
        const uint32_t* As = smu + (c % 3) * 4096;
        const uint32_t* Ws = smu + 12288 + (c % 3) * 4096;
#pragma unroll
        for (int kp = 0; kp < 2; kp++) {
            uint32_t a[4][2][4];
#pragma unroll
            for (int mi = 0; mi < 4; mi++)
#pragma unroll
                for (int kk = 0; kk < 2; kk++) {
                    uint4 av = *((const uint4*)(As + ((wm * 4 + mi) * 4 + kp * 2 + kk) * 128) + lane);
                    a[mi][kk][0] = av.x; a[mi][kk][1] = av.y;
                    a[mi][kk][2] = av.z; a[mi][kk][3] = av.w;
                }
#pragma unroll
            for (int ni = 0; ni < 8; ni++) {
                uint4 bv = *((const uint4*)(Ws + ((wn * 8 + ni) * 2 + kp) * 128) + lane);
#pragma unroll
                for (int mi = 0; mi < 4; mi++) {
                    mma16(acc[mi][ni], a[mi][0], bv.x, bv.y);
                    mma16(acc[mi][ni], a[mi][1], bv.z, bv.w);
                }
            }
        }
    }
#undef GISSUE
}

// ======================================================================
// Fused qkv projections. z=0: Q + RoPE -> Qp (A-frag per bh).
// z=1: K + RoPE -> Kp (B2). z=2: V transposed -> Vp (B2, k=s, n=d).
// Warp = 64 rows x one 64-col head.
// ======================================================================
__global__ void __launch_bounds__(128, 2) gemm_qkv()
{
    extern __shared__ uint32_t smu[];
    const int z = blockIdx.z;
    int row0, col0;
    const uint32_t *Ab, *Bp;
    if (z == 2) {
        row0 = blockIdx.x * 128;                 // over Dd (V out-dim)
        col0 = blockIdx.y * 128;                 // over Mm (s)
        Ab = g_wvA + (size_t)(row0 >> 4) * (Dd / 16) * 128;
        Bp = g_xB  + (size_t)(col0 >> 3) * (Dd / 32) * 128;
    } else {
        row0 = blockIdx.y * 128;                 // over Mm (s)
        col0 = blockIdx.x * 128;                 // over Dd
        Ab = g_xA + (size_t)(row0 >> 4) * (Dd / 16) * 128;
        Bp = ((z == 0) ? g_wqB : g_wkB) + (size_t)(col0 >> 3) * (Dd / 32) * 128;
    }

    float acc[4][8][4];
    gemm_main(Ab, Bp, smu, acc);

    const int tid = threadIdx.x;
    const int w = tid >> 5, lane = tid & 31;
    const int gid = lane >> 2, sub = lane & 3;
    const int wm = w >> 1, wn = w & 1;

    if (z == 2) {
        const int bb = col0 >> 11;
        const int sB = (col0 & 2047) + wn * 64;
        const int dW = row0 + wm * 64;
        const int bh = bb * 16 + (dW >> 6);
        uint32_t* dst = g_vp + (size_t)bh * 65536;
#pragma unroll
        for (int d8 = 0; d8 < 8; d8++) {
            int mi = d8 >> 1, hh = d8 & 1;
#pragma unroll
            for (int sp = 0; sp < 2; sp++) {
                uint4 o = make_uint4(
                    pk(acc[mi][4 * sp][2 * hh],     acc[mi][4 * sp][2 * hh + 1]),
                    pk(acc[mi][4 * sp + 1][2 * hh], acc[mi][4 * sp + 1][2 * hh + 1]),
                    pk(acc[mi][4 * sp + 2][2 * hh], acc[mi][4 * sp + 2][2 * hh + 1]),
                    pk(acc[mi][4 * sp + 3][2 * hh], acc[mi][4 * sp + 3][2 * hh + 1]));
                *(uint4*)(dst + (((size_t)(sB >> 5) + sp) * 8 + d8) * 128 + lane * 4) = o;
            }
        }
        return;
    }

    // z 0/1: RoPE in registers (pair d, d+32 = acc[..][ni], acc[..][ni+4])
    const int bb = row0 >> 11;
    const int sB = (row0 & 2047) + wm * 64;
    const int bh = bb * 16 + (col0 >> 6) + wn;
#pragma unroll
    for (int mi = 0; mi < 4; mi++) {
#pragma unroll
        for (int hh = 0; hh < 2; hh++) {
            int s = sB + mi * 16 + gid + 8 * hh;
#pragma unroll
            for (int ni = 0; ni < 4; ni++) {
                float2 c2 = *(const float2*)&g_cos[s * 32 + ni * 8 + 2 * sub];
                float2 s2 = *(const float2*)&g_sin[s * 32 + ni * 8 + 2 * sub];
                {
                    int cc = 2 * hh;
                    float x1 = acc[mi][ni][cc], x2 = acc[mi][ni + 4][cc];
                    acc[mi][ni][cc]     = x1 * c2.x - x2 * s2.x;
                    acc[mi][ni + 4][cc] = x2 * c2.x + x1 * s2.x;
                }
                {
                    int cc = 2 * hh + 1;
                    float x1 = acc[mi][ni][cc], x2 = acc[mi][ni + 4][cc];
                    acc[mi][ni][cc]     = x1 * c2.y - x2 * s2.y;
                    acc[mi][ni + 4][cc] = x2 * c2.y + x1 * s2.y;
                }
            }
        }
    }

    if (z == 0) {
        uint32_t* dst = g_qp + (size_t)bh * 65536;
#pragma unroll
        for (int mi = 0; mi < 4; mi++) {
#pragma unroll
            for (int j = 0; j < 4; j++) {
                uint4 o = make_uint4(
                    pk(acc[mi][2 * j][0],     acc[mi][2 * j][1]),
                    pk(acc[mi][2 * j][2],     acc[mi][2 * j][3]),
                    pk(acc[mi][2 * j + 1][0], acc[mi][2 * j + 1][1]),
                    pk(acc[mi][2 * j + 1][2], acc[mi][2 * j + 1][3]));
                *(uint4*)(dst + ((size_t)((sB >> 4) + mi) * 4 + j) * 128 + lane * 4) = o;
            }
        }
    } else {
        uint32_t* dst = g_kp + (size_t)bh * 65536;
#pragma unroll
        for (int s8 = 0; s8 < 8; s8++) {
            int mi = s8 >> 1, hh = s8 & 1;
#pragma unroll
            for (int jp = 0; jp < 2; jp++) {
                uint4 o = make_uint4(
                    pk(acc[mi][4 * jp][2 * hh],     acc[mi][4 * jp][2 * hh + 1]),
                    pk(acc[mi][4 * jp + 1][2 * hh], acc[mi][4 * jp + 1][2 * hh + 1]),
                    pk(acc[mi][4 * jp + 2][2 * hh], acc[mi][4 * jp + 2][2 * hh + 1]),
                    pk(acc[mi][4 * jp + 3][2 * hh], acc[mi][4 * jp + 3][2 * hh + 1]));
                *(uint4*)(dst + (((size_t)((sB >> 3) + s8)) * 2 + jp) * 128 + lane * 4) = o;
            }
        }
    }
}

// ======================================================================
// Output projection: out = Op @ wo^T (fp32 row-major result)
// ======================================================================
__global__ void __launch_bounds__(128, 2) gemm_o(float* __restrict__ C)
{
    extern __shared__ uint32_t smu[];
    const int row0 = blockIdx.y * 128, col0 = blockIdx.x * 128;
    const uint32_t* Ab = g_op  + (size_t)(row0 >> 4) * (Dd / 16) * 128;
    const uint32_t* Bp = g_woB + (size_t)(col0 >> 3) * (Dd / 32) * 128;

    float acc[4][8][4];
    gemm_main(Ab, Bp, smu, acc);

    const int tid = threadIdx.x;
    const int w = tid >> 5, lane = tid & 31;
    const int gid = lane >> 2, sub = lane & 3;
    const int wm = w >> 1, wn = w & 1;
#pragma unroll
    for (int mi = 0; mi < 4; mi++) {
        int row = row0 + wm * 64 + mi * 16 + gid;
#pragma unroll
        for (int ni = 0; ni < 8; ni++) {
            int col = col0 + wn * 64 + ni * 8 + 2 * sub;
            *(float2*)(C + (size_t)row * Dd + col) =
                make_float2(acc[mi][ni][0], acc[mi][ni][1]);
            *(float2*)(C + (size_t)(row + 8) * Dd + col) =
                make_float2(acc[mi][ni][2], acc[mi][ni][3]);
        }
    }
}

// ======================================================================
// Flash attention, causal, fp16 m16n8k16, B2-frag K/V.
// 8 warps (256 thr), 16 q-rows x 64 cols per warp; 2 CTA/SM.
// PAIRED q-tiles {NT-1-bx, bx}: constant 34 iterations per CTA.
// Softmax p generated with ex2.approx.f16x2 (2 probs / MUFU op);
// rsum accumulated from the SAME rounded p used in the PV MMA.
// ======================================================================
#define FQ 0
#define FK(b) (4096 + (b)*2048)
#define FV(b) (10240 + (b)*2048)
#define FA_SMEM (16384*4)
#define SCL 0.180336877f    // 0.125 * log2(e)
#define NT (Ss/128)         // 16 q-tiles per (b,h)

__global__ void __launch_bounds__(256, 2) flash_tc()
{
    extern __shared__ uint32_t smu[];
    const uint32_t sb = smem_u32(smu);

    const int tid = threadIdx.x;
    const int w = tid >> 5, lane = tid & 31;
    const int gid = lane >> 2, sub = lane & 3;

    const int bh = blockIdx.y;
    const int bb = bh >> 4, h = bh & 15;

    const size_t bho = (size_t)bh * 65536;
    const uint32_t* Kg = g_kp + bho;
    const uint32_t* Vg = g_vp + bho;

#pragma unroll
    for (int t = 0; t < 2; t++) {
        const int qt = t ? (int)blockIdx.x : (NT - 1 - (int)blockIdx.x);
        const int q0 = qt * 128;
        const uint32_t* Qg = g_qp + bho + (size_t)qt * 4096;
        const int nkt = 2 * qt + 2;

#pragma unroll
        for (int i = 0; i < 4; i++) {
            int f = tid + i * 256;
            cp16(sb + (FQ + f * 4) * 4, Qg + f * 4);
        }
        CP_COMMIT();
#pragma unroll
        for (int i = 0; i < 2; i++) {
            int f = tid + i * 256;
            cp16(sb + (FK(0) + f * 4) * 4, Kg + f * 4);
            cp16(sb + (FV(0) + f * 4) * 4, Vg + f * 4);
        }
        CP_COMMIT();
#pragma unroll
        for (int i = 0; i < 2; i++) {
            int f = tid + i * 256;
            cp16(sb + (FK(1) + f * 4) * 4, Kg + 2048 + f * 4);
            cp16(sb + (FV(1) + f * 4) * 4, Vg + 2048 + f * 4);
        }
        CP_COMMIT();

        CP_WAIT2();
        __syncthreads();

        uint32_t qf[4][4];
#pragma unroll
        for (int ks = 0; ks < 4; ks++) {
            uint4 av = *((const uint4*)(smu + FQ + (w * 4 + ks) * 128) + lane);
            qf[ks][0] = av.x; qf[ks][1] = av.y;
            qf[ks][2] = av.z; qf[ks][3] = av.w;
        }

        float m_i[2] = {-1e30f, -1e30f};
        float l_i[2] = {0.0f, 0.0f};
        float acc[8][4];
#pragma unroll
        for (int ni = 0; ni < 8; ni++)
#pragma unroll
            for (int cc = 0; cc < 4; cc++) acc[ni][cc] = 0.0f;

        for (int kb = 0; kb < nkt; kb++) {
            const int b = kb % 3;
            const uint32_t* Ks = smu + FK(b);
            const uint32_t* Vs = smu + FV(b);

            if (kb + 1 < nkt) { CP_WAIT1(); } else { CP_WAIT0(); }
            __syncthreads();

            if (kb + 2 < nkt) {
                const int b2 = (kb + 2) % 3;
                const uint32_t* Kn = Kg + (size_t)(kb + 2) * 2048;
                const uint32_t* Vn = Vg + (size_t)(kb + 2) * 2048;
#pragma unroll
                for (int i = 0; i < 2; i++) {
                    int f = tid + i * 256;
                    cp16(sb + (FK(b2) + f * 4) * 4, Kn + f * 4);
                    cp16(sb + (FV(b2) + f * 4) * 4, Vn + f * 4);
                }
                CP_COMMIT();
            }

            if (kb == 2 * qt + 1 && w < 4) continue;

            // ---- S = Q K^T ----
            float s[8][4];
#pragma unroll
            for (int ni = 0; ni < 8; ni++)
#pragma unroll
                for (int cc = 0; cc < 4; cc++) s[ni][cc] = 0.0f;

#pragma unroll
            for (int kp = 0; kp < 2; kp++) {
#pragma unroll
                for (int ni = 0; ni < 8; ni++) {
                    uint4 bv = *((const uint4*)(Ks + (ni * 2 + kp) * 128) + lane);
                    mma16(s[ni], qf[2 * kp],     bv.x, bv.y);
                    mma16(s[ni], qf[2 * kp + 1], bv.z, bv.w);
                }
            }

            // ---- scale + causal mask + online softmax (log2 domain) ----
            const int k0 = kb * 64;
            const bool mt = (kb >= 2 * qt);
            const int r0g = q0 + w * 16 + gid;
            float rmax[2] = {-1e30f, -1e30f};
#pragma unroll
            for (int ni = 0; ni < 8; ni++) {
                int colb = k0 + ni * 8 + 2 * sub;
#pragma unroll
                for (int cc = 0; cc < 4; cc++) {
                    float sv = s[ni][cc] * SCL;
                    if (mt) {
                        int row = r0g + ((cc >> 1) << 3);
                        int col = colb + (cc & 1);
                        if (col > row) sv = -1e30f;
                    }
                    s[ni][cc] = sv;
                    rmax[cc >> 1] = fmaxf(rmax[cc >> 1], sv);
                }
            }
#pragma unroll
            for (int o = 1; o <= 2; o <<= 1) {
                rmax[0] = fmaxf(rmax[0], __shfl_xor_sync(0xffffffffu, rmax[0], o));
                rmax[1] = fmaxf(rmax[1], __shfl_xor_sync(0xffffffffu, rmax[1], o));
            }
            float mnew0 = fmaxf(m_i[0], rmax[0]);
            float mnew1 = fmaxf(m_i[1], rmax[1]);
            float corr0 = exp2f(m_i[0] - mnew0);
            float corr1 = exp2f(m_i[1] - mnew1);
            m_i[0] = mnew0; m_i[1] = mnew1;

            // ---- p = 2^(s-m) via f16x2 MUFU; rsum from the rounded p ----
            uint32_t pa[4][4];
            float rsum[2] = {0.0f, 0.0f};
#pragma unroll
            for (int ni = 0; ni < 8; ni++) {
                uint32_t e0 = h2exp2(pk(s[ni][0] - mnew0, s[ni][1] - mnew0));
                uint32_t e1 = h2exp2(pk(s[ni][2] - mnew1, s[ni][3] - mnew1));
                pa[ni >> 1][(ni & 1) * 2]     = e0;
                pa[ni >> 1][(ni & 1) * 2 + 1] = e1;
                float2 f0 = h2f2(e0);
                float2 f1 = h2f2(e1);
                rsum[0] += f0.x + f0.y;
                rsum[1] += f1.x + f1.y;
                acc[ni][0] *= corr0; acc[ni][1] *= corr0;
                acc[ni][2] *= corr1; acc[ni][3] *= corr1;
            }
#pragma unroll
            for (int o = 1; o <= 2; o <<= 1) {
                rsum[0] += __shfl_xor_sync(0xffffffffu, rsum[0], o);
                rsum[1] += __shfl_xor_sync(0xffffffffu, rsum[1], o);
            }
            l_i[0] = l_i[0] * corr0 + rsum[0];
            l_i[1] = l_i[1] * corr1 + rsum[1];

            // ---- O += P V (V in B2) ----
#pragma unroll
            for (int jp = 0; jp < 2; jp++) {
#pragma unroll
                for (int ni = 0; ni < 8; ni++) {
                    uint4 bv = *((const uint4*)(Vs + (jp * 8 + ni) * 128) + lane);
                    mma16(acc[ni], pa[2 * jp],     bv.x, bv.y);
                    mma16(acc[ni], pa[2 * jp + 1], bv.z, bv.w);
                }
            }
        }

        {
            int m16 = bb * 128 + qt * 8 + w;
            float inv0 = 1.0f / l_i[0];
            float inv1 = 1.0f / l_i[1];
#pragma unroll
            for (int j = 0; j < 4; j++) {
                uint4 o = make_uint4(
                    pk(acc[2 * j][0] * inv0,     acc[2 * j][1] * inv0),
                    pk(acc[2 * j][2] * inv1,     acc[2 * j][3] * inv1),
                    pk(acc[2 * j + 1][0] * inv0, acc[2 * j + 1][1] * inv0),
                    pk(acc[2 * j + 1][2] * inv1, acc[2 * j + 1][3] * inv1));
                *(uint4*)(g_op + ((size_t)m16 * (Dd / 16) + h * 4 + j) * 128 + lane * 4) = o;
            }
        }
        __syncthreads();
    }
}

// ======================================================================
// Launch
// ======================================================================
extern "C" void kernel_launch(void* const* d_in, const int* in_sizes, int n_in,
                              void* d_out, int out_size)
{
    const float* x  = (const float*)d_in[0];
    const float* wq = (const float*)d_in[1];
    const float* wk = (const float*)d_in[2];
    const float* wv = (const float*)d_in[3];
    const float* wo = (const float*)d_in[4];
    float* out = (float*)d_out;

    cudaFuncSetAttribute(gemm_qkv, cudaFuncAttributeMaxDynamicSharedMemorySize, GEMM_SMEM);
    cudaFuncSetAttribute(gemm_o,   cudaFuncAttributeMaxDynamicSharedMemorySize, GEMM_SMEM);
    cudaFuncSetAttribute(flash_tc, cudaFuncAttributeMaxDynamicSharedMemorySize, FA_SMEM);

    // 0) ONE prep kernel: RoPE tables + all operand permutes
    prep<<<dim3(Mm / 64, Dd / 64, 2), 256>>>(x, wq, wk, wo, wv);

    // 1) fused q/k/v projections + RoPE + frag-permute epilogues
    gemm_qkv<<<dim3(Dd / 128, Mm / 128, 3), 128, GEMM_SMEM>>>();

    // 2) causal flash attention (8-warp CTAs, balanced paired q-tiles)
    flash_tc<<<dim3(NT / 2, Bb * Hh), 256, FA_SMEM>>>();

    // 3) output projection
    gemm_o<<<dim3(Dd / 128, Mm / 128), 128, GEMM_SMEM>>>(out);
}

// round 15
// speedup vs baseline: 1.0815x; 1.0003x over previous
#include <cuda_runtime.h>
#include <cuda_fp16.h>
#include <math.h>
#include <stdint.h>

// Problem constants
#define Bb 2
#define Ss 2048
#define Dd 1024
#define Hh 16
#define HDh 64
#define Mm (Bb*Ss)   // 4096

// Scratch (device globals), all fp16-packed uint32 unless noted
// B2 layout: superblocks (n8, k32) of 128 words; lane l owns l*4+{0..3}.
// A layout: blocks (m16, k16) of 128 words; lane l owns l*4+{0..3}.
__device__ uint32_t g_xA[Mm*Dd/2];     // x, A-frag
__device__ uint32_t g_xB[Mm*Dd/2];     // x, B2-frag (n=s)
__device__ uint32_t g_wqB[Dd*Dd/2];    // B2
__device__ uint32_t g_wkB[Dd*Dd/2];    // B2
__device__ uint32_t g_woB[Dd*Dd/2];    // B2
__device__ uint32_t g_wvA[Dd*Dd/2];    // wv, A-frag (for transposed V gemm)
__device__ uint32_t g_qp[Mm*Dd/2];     // Q per (b,h), A-frag
__device__ uint32_t g_kp[Mm*Dd/2];     // K per (b,h), B2 (n=s, k=d)
__device__ uint32_t g_vp[Mm*Dd/2];     // V per (b,h), B2 (k=s, n=d)
__device__ uint32_t g_op[Mm*Dd/2];     // attn out, global A-frag
__device__ float    g_cos[Ss*32];
__device__ float    g_sin[Ss*32];

// ======================================================================
// Helpers
// ======================================================================
__device__ __forceinline__ uint32_t smem_u32(const void* p) {
    uint32_t a;
    asm("{ .reg .u64 t; cvta.to.shared.u64 t, %1; cvt.u32.u64 %0, t; }"
        : "=r"(a) : "l"(p));
    return a;
}
__device__ __forceinline__ uint32_t pk(float a, float b) {
    __half2 h = __floats2half2_rn(a, b);
    return *reinterpret_cast<uint32_t*>(&h);
}
// 2^x on two fp16 lanes in one MUFU op
__device__ __forceinline__ uint32_t h2exp2(uint32_t h) {
    uint32_t e;
    asm("ex2.approx.f16x2 %0, %1;" : "=r"(e) : "r"(h));
    return e;
}
__device__ __forceinline__ float2 h2f2(uint32_t h) {
    __half2 v = *reinterpret_cast<__half2*>(&h);
    return __half22float2(v);
}
__device__ __forceinline__ void mma16(float* d, const uint32_t* a,
                                      uint32_t b0, uint32_t b1) {
    asm volatile(
        "mma.sync.aligned.m16n8k16.row.col.f32.f16.f16.f32 "
        "{%0,%1,%2,%3}, {%4,%5,%6,%7}, {%8,%9}, {%0,%1,%2,%3};"
        : "+f"(d[0]), "+f"(d[1]), "+f"(d[2]), "+f"(d[3])
        : "r"(a[0]), "r"(a[1]), "r"(a[2]), "r"(a[3]), "r"(b0), "r"(b1));
}
__device__ __forceinline__ void cp16(uint32_t dst, const void* src) {
    asm volatile("cp.async.cg.shared.global [%0], [%1], 16;"
                 :: "r"(dst), "l"(src) : "memory");
}
#define CP_COMMIT() asm volatile("cp.async.commit_group;" ::: "memory")
#define CP_WAIT0()  asm volatile("cp.async.wait_group 0;" ::: "memory")
#define CP_WAIT1()  asm volatile("cp.async.wait_group 1;" ::: "memory")
#define CP_WAIT2()  asm volatile("cp.async.wait_group 2;" ::: "memory")

// ======================================================================
// prep: ONE kernel for RoPE tables + all operand permutes.
// ======================================================================
__global__ __launch_bounds__(256) void prep(
    const float* __restrict__ x,
    const float* __restrict__ wq, const float* __restrict__ wk,
    const float* __restrict__ wo, const float* __restrict__ wv)
{
    __shared__ float ts[64][68];
    const int tid = threadIdx.x;
    const int w = tid >> 5, l = tid & 31;
    const int gid = l >> 2, sub = l & 3;

    if (blockIdx.z == 0) {
        if (tid < 64) {
            int idx = (int)(blockIdx.x * 16 + blockIdx.y) * 64 + tid;
            int s = idx >> 5, i = idx & 31;
            double inv = pow(10000.0, -((double)(2 * i)) / (double)HDh);
            double sd, cd;
            sincos((double)s * inv, &sd, &cd);
            g_cos[idx] = (float)cd;
            g_sin[idx] = (float)sd;
        }
        const int r0 = blockIdx.x * 64, c0 = blockIdx.y * 64;
#pragma unroll
        for (int i = 0; i < 4; i++) {
            int f = tid + i * 256;
            int r = f >> 4, c4 = (f & 15) << 2;
            *(float4*)&ts[r][c4] = *(const float4*)(x + (size_t)(r0 + r) * Dd + c0 + c4);
        }
        __syncthreads();
        {
            int mi = w >> 1;
#pragma unroll
            for (int jj = 0; jj < 2; jj++) {
                int j = (w & 1) * 2 + jj;
                int r = mi * 16 + gid, d = j * 16 + 2 * sub;
                uint4 o = make_uint4(
                    pk(ts[r][d],         ts[r][d + 1]),
                    pk(ts[r + 8][d],     ts[r + 8][d + 1]),
                    pk(ts[r][d + 8],     ts[r][d + 9]),
                    pk(ts[r + 8][d + 8], ts[r + 8][d + 9]));
                *(uint4*)(g_xA + ((size_t)(r0 / 16 + mi) * (Dd / 16) + (c0 / 16 + j)) * 128 + l * 4) = o;
            }
        }
        {
            int n = w * 8 + gid;
#pragma unroll
            for (int kp = 0; kp < 2; kp++) {
                int d0 = kp * 32 + 2 * sub;
                uint4 o = make_uint4(
                    pk(ts[n][d0],      ts[n][d0 + 1]),
                    pk(ts[n][d0 + 8],  ts[n][d0 + 9]),
                    pk(ts[n][d0 + 16], ts[n][d0 + 17]),
                    pk(ts[n][d0 + 24], ts[n][d0 + 25]));
                *(uint4*)(g_xB + ((size_t)(r0 / 8 + w) * (Dd / 32) + (c0 / 32 + kp)) * 128 + l * 4) = o;
            }
        }
        return;
    }

    const int wsel = blockIdx.x >> 4;
    const float* W = (wsel == 0) ? wq : (wsel == 1) ? wk : (wsel == 2) ? wo : wv;
    const int n0 = (blockIdx.x & 15) * 64, k0 = blockIdx.y * 64;
#pragma unroll
    for (int i = 0; i < 4; i++) {
        int f = tid + i * 256;
        int r = f >> 4, c4 = (f & 15) << 2;
        *(float4*)&ts[r][c4] = *(const float4*)(W + (size_t)(n0 + r) * Dd + k0 + c4);
    }
    __syncthreads();

    if (wsel == 3) {
        int mi = w >> 1;
#pragma unroll
        for (int jj = 0; jj < 2; jj++) {
            int j = (w & 1) * 2 + jj;
            int r = mi * 16 + gid, d = j * 16 + 2 * sub;
            uint4 o = make_uint4(
                pk(ts[r][d],         ts[r][d + 1]),
                pk(ts[r + 8][d],     ts[r + 8][d + 1]),
                pk(ts[r][d + 8],     ts[r][d + 9]),
                pk(ts[r + 8][d + 8], ts[r + 8][d + 9]));
            *(uint4*)(g_wvA + ((size_t)(n0 / 16 + mi) * (Dd / 16) + (k0 / 16 + j)) * 128 + l * 4) = o;
        }
        return;
    }
    uint32_t* D = (wsel == 0) ? g_wqB : (wsel == 1) ? g_wkB : g_woB;
    int n = w * 8 + gid;
#pragma unroll
    for (int kp = 0; kp < 2; kp++) {
        int d0 = kp * 32 + 2 * sub;
        uint4 o = make_uint4(
            pk(ts[n][d0],      ts[n][d0 + 1]),
            pk(ts[n][d0 + 8],  ts[n][d0 + 9]),
            pk(ts[n][d0 + 16], ts[n][d0 + 17]),
            pk(ts[n][d0 + 24], ts[n][d0 + 25]));
        *(uint4*)(D + ((size_t)(n0 / 8 + w) * (Dd / 32) + (k0 / 32 + kp)) * 128 + l * 4) = o;
    }
}

// ======================================================================
// GEMM mainloop: CTA 128x128, 128 thr, 4 warps of 64x64.
// A streamed DIRECTLY from gmem (already fragment-laid-out) via LDG.128;
// B through 3-stage cp.async smem (B-only: 48 KB/CTA).
// ======================================================================
#define GEMM_SMEM 49152

__device__ __forceinline__ void gemm_main(
    const uint32_t* __restrict__ Ab, const uint32_t* __restrict__ Bp,
    uint32_t* smu, float acc[4][8][4])
{
    const uint32_t sb = smem_u32(smu);
    const int tid = threadIdx.x;
    const int w = tid >> 5, lane = tid & 31;
    const int wm = w >> 1, wn = w & 1;

    const uint32_t* srcw[8];
#pragma unroll
    for (int i = 0; i < 8; i++) {
        int f = tid + i * 128;
        int bw = f >> 5, wb = f & 31;
        srcw[i] = Bp + ((size_t)(bw >> 1) * (Dd / 32) + (bw & 1)) * 128 + wb * 4;
    }
    // this warp's A fragment base: m16 blocks wm*4 .. wm*4+3
    const uint32_t* Aw = Ab + (size_t)(wm * 4) * (Dd / 16) * 128 + lane * 4;

#pragma unroll
    for (int mi = 0; mi < 4; mi++)
#pragma unroll
        for (int ni = 0; ni < 8; ni++)
#pragma unroll
            for (int cc = 0; cc < 4; cc++) acc[mi][ni][cc] = 0.0f;

#define GISSUE(c) do { int _b = (c) % 3; \
    _Pragma("unroll") \
    for (int i = 0; i < 8; i++) { int f = tid + i * 128; \
        cp16(sb + (_b * 4096 + f * 4) * 4, srcw[i] + (size_t)(c) * 256); } \
    CP_COMMIT(); } while (0)

    GISSUE(0);
    GISSUE(1);
    for (int c = 0; c < 16; c++) {
        // A fragments for this chunk: 16 direct LDG.128 (MLP=16)
        uint32_t av[4][4][4];
#pragma unroll
        for (int mi = 0; mi < 4; mi++)
#pragma unroll
            for (int kk = 0; kk < 4; kk++) {
                uint4 t = *(const uint4*)(Aw + ((size_t)mi * (Dd / 16) + c * 4 + kk) * 128);
                av[mi][kk][0] = t.x; av[mi][kk][1] = t.y;
                av[mi][kk][2] = t.z; av[mi][kk][3] = t.w;
            }

        if (c + 1 < 16) { CP_WAIT1(); } else { CP_WAIT0(); }
        __syncthreads();
        if (c + 2 < 16) GISSUE(c + 2);

        const uint32_t* Ws = smu + (c % 3) * 4096;
#pragma unroll
        for (int kp = 0; kp < 2; kp++) {
#pragma unroll
            for (int ni = 0; ni < 8; ni++) {
                uint4 bv = *((const uint4*)(Ws + ((wn * 8 + ni) * 2 + kp) * 128) + lane);
#pragma unroll
                for (int mi = 0; mi < 4; mi++) {
                    mma16(acc[mi][ni], av[mi][kp * 2],     bv.x, bv.y);
                    mma16(acc[mi][ni], av[mi][kp * 2 + 1], bv.z, bv.w);
                }
            }
        }
        __syncthreads();   // all warps done reading Ws before GISSUE overwrites
    }
#undef GISSUE
}

// ======================================================================
// Fused qkv projections. z=0: Q + RoPE -> Qp (A-frag per bh).
// z=1: K + RoPE -> Kp (B2). z=2: V transposed -> Vp (B2, k=s, n=d).
// Warp = 64 rows x one 64-col head.
// ======================================================================
__global__ void __launch_bounds__(128, 2) gemm_qkv()
{
    extern __shared__ uint32_t smu[];
    const int z = blockIdx.z;
    int row0, col0;
    const uint32_t *Ab, *Bp;
    if (z == 2) {
        row0 = blockIdx.x * 128;                 // over Dd (V out-dim)
        col0 = blockIdx.y * 128;                 // over Mm (s)
        Ab = g_wvA + (size_t)(row0 >> 4) * (Dd / 16) * 128;
        Bp = g_xB  + (size_t)(col0 >> 3) * (Dd / 32) * 128;
    } else {
        row0 = blockIdx.y * 128;                 // over Mm (s)
        col0 = blockIdx.x * 128;                 // over Dd
        Ab = g_xA + (size_t)(row0 >> 4) * (Dd / 16) * 128;
        Bp = ((z == 0) ? g_wqB : g_wkB) + (size_t)(col0 >> 3) * (Dd / 32) * 128;
    }

    float acc[4][8][4];
    gemm_main(Ab, Bp, smu, acc);

    const int tid = threadIdx.x;
    const int w = tid >> 5, lane = tid & 31;
    const int gid = lane >> 2, sub = lane & 3;
    const int wm = w >> 1, wn = w & 1;

    if (z == 2) {
        const int bb = col0 >> 11;
        const int sB = (col0 & 2047) + wn * 64;
        const int dW = row0 + wm * 64;
        const int bh = bb * 16 + (dW >> 6);
        uint32_t* dst = g_vp + (size_t)bh * 65536;
#pragma unroll
        for (int d8 = 0; d8 < 8; d8++) {
            int mi = d8 >> 1, hh = d8 & 1;
#pragma unroll
            for (int sp = 0; sp < 2; sp++) {
                uint4 o = make_uint4(
                    pk(acc[mi][4 * sp][2 * hh],     acc[mi][4 * sp][2 * hh + 1]),
                    pk(acc[mi][4 * sp + 1][2 * hh], acc[mi][4 * sp + 1][2 * hh + 1]),
                    pk(acc[mi][4 * sp + 2][2 * hh], acc[mi][4 * sp + 2][2 * hh + 1]),
                    pk(acc[mi][4 * sp + 3][2 * hh], acc[mi][4 * sp + 3][2 * hh + 1]));
                *(uint4*)(dst + (((size_t)(sB >> 5) + sp) * 8 + d8) * 128 + lane * 4) = o;
            }
        }
        return;
    }

    // z 0/1: RoPE in registers (pair d, d+32 = acc[..][ni], acc[..][ni+4])
    const int bb = row0 >> 11;
    const int sB = (row0 & 2047) + wm * 64;
    const int bh = bb * 16 + (col0 >> 6) + wn;
#pragma unroll
    for (int mi = 0; mi < 4; mi++) {
#pragma unroll
        for (int hh = 0; hh < 2; hh++) {
            int s = sB + mi * 16 + gid + 8 * hh;
#pragma unroll
            for (int ni = 0; ni < 4; ni++) {
                float2 c2 = *(const float2*)&g_cos[s * 32 + ni * 8 + 2 * sub];
                float2 s2 = *(const float2*)&g_sin[s * 32 + ni * 8 + 2 * sub];
                {
                    int cc = 2 * hh;
                    float x1 = acc[mi][ni][cc], x2 = acc[mi][ni + 4][cc];
                    acc[mi][ni][cc]     = x1 * c2.x - x2 * s2.x;
                    acc[mi][ni + 4][cc] = x2 * c2.x + x1 * s2.x;
                }
                {
                    int cc = 2 * hh + 1;
                    float x1 = acc[mi][ni][cc], x2 = acc[mi][ni + 4][cc];
                    acc[mi][ni][cc]     = x1 * c2.y - x2 * s2.y;
                    acc[mi][ni + 4][cc] = x2 * c2.y + x1 * s2.y;
                }
            }
        }
    }

    if (z == 0) {
        uint32_t* dst = g_qp + (size_t)bh * 65536;
#pragma unroll
        for (int mi = 0; mi < 4; mi++) {
#pragma unroll
            for (int j = 0; j < 4; j++) {
                uint4 o = make_uint4(
                    pk(acc[mi][2 * j][0],     acc[mi][2 * j][1]),
                    pk(acc[mi][2 * j][2],     acc[mi][2 * j][3]),
                    pk(acc[mi][2 * j + 1][0], acc[mi][2 * j + 1][1]),
                    pk(acc[mi][2 * j + 1][2], acc[mi][2 * j + 1][3]));
                *(uint4*)(dst + ((size_t)((sB >> 4) + mi) * 4 + j) * 128 + lane * 4) = o;
            }
        }
    } else {
        uint32_t* dst = g_kp + (size_t)bh * 65536;
#pragma unroll
        for (int s8 = 0; s8 < 8; s8++) {
            int mi = s8 >> 1, hh = s8 & 1;
#pragma unroll
            for (int jp = 0; jp < 2; jp++) {
                uint4 o = make_uint4(
                    pk(acc[mi][4 * jp][2 * hh],     acc[mi][4 * jp][2 * hh + 1]),
                    pk(acc[mi][4 * jp + 1][2 * hh], acc[mi][4 * jp + 1][2 * hh + 1]),
                    pk(acc[mi][4 * jp + 2][2 * hh], acc[mi][4 * jp + 2][2 * hh + 1]),
                    pk(acc[mi][4 * jp + 3][2 * hh], acc[mi][4 * jp + 3][2 * hh + 1]));
                *(uint4*)(dst + (((size_t)((sB >> 3) + s8)) * 2 + jp) * 128 + lane * 4) = o;
            }
        }
    }
}

// ======================================================================
// Output projection: out = Op @ wo^T (fp32 row-major result)
// ======================================================================
__global__ void __launch_bounds__(128, 2) gemm_o(float* __restrict__ C)
{
    extern __shared__ uint32_t smu[];
    const int row0 = blockIdx.y * 128, col0 = blockIdx.x * 128;
    const uint32_t* Ab = g_op  + (size_t)(row0 >> 4) * (Dd / 16) * 128;
    const uint32_t* Bp = g_woB + (size_t)(col0 >> 3) * (Dd / 32) * 128;

    float acc[4][8][4];
    gemm_main(Ab, Bp, smu, acc);

    const int tid = threadIdx.x;
    const int w = tid >> 5, lane = tid & 31;
    const int gid = lane >> 2, sub = lane & 3;
    const int wm = w >> 1, wn = w & 1;
#pragma unroll
    for (int mi = 0; mi < 4; mi++) {
        int row = row0 + wm * 64 + mi * 16 + gid;
#pragma unroll
        for (int ni = 0; ni < 8; ni++) {
            int col = col0 + wn * 64 + ni * 8 + 2 * sub;
            *(float2*)(C + (size_t)row * Dd + col) =
                make_float2(acc[mi][ni][0], acc[mi][ni][1]);
            *(float2*)(C + (size_t)(row + 8) * Dd + col) =
                make_float2(acc[mi][ni][2], acc[mi][ni][3]);
        }
    }
}

// ======================================================================
// Flash attention, causal, fp16 m16n8k16, B2-frag K/V (unchanged R14).
// 8 warps (256 thr), 16 q-rows x 64 cols per warp; 2 CTA/SM.
// PAIRED q-tiles {NT-1-bx, bx}: constant 34 iterations per CTA.
// ======================================================================
#define FQ 0
#define FK(b) (4096 + (b)*2048)
#define FV(b) (10240 + (b)*2048)
#define FA_SMEM (16384*4)
#define SCL 0.180336877f    // 0.125 * log2(e)
#define NT (Ss/128)         // 16 q-tiles per (b,h)

__global__ void __launch_bounds__(256, 2) flash_tc()
{
    extern __shared__ uint32_t smu[];
    const uint32_t sb = smem_u32(smu);

    const int tid = threadIdx.x;
    const int w = tid >> 5, lane = tid & 31;
    const int gid = lane >> 2, sub = lane & 3;

    const int bh = blockIdx.y;
    const int bb = bh >> 4, h = bh & 15;

    const size_t bho = (size_t)bh * 65536;
    const uint32_t* Kg = g_kp + bho;
    const uint32_t* Vg = g_vp + bho;

#pragma unroll
    for (int t = 0; t < 2; t++) {
        const int qt = t ? (int)blockIdx.x : (NT - 1 - (int)blockIdx.x);
        const int q0 = qt * 128;
        const uint32_t* Qg = g_qp + bho + (size_t)qt * 4096;
        const int nkt = 2 * qt + 2;

#pragma unroll
        for (int i = 0; i < 4; i++) {
            int f = tid + i * 256;
            cp16(sb + (FQ + f * 4) * 4, Qg + f * 4);
        }
        CP_COMMIT();
#pragma unroll
        for (int i = 0; i < 2; i++) {
            int f = tid + i * 256;
            cp16(sb + (FK(0) + f * 4) * 4, Kg + f * 4);
            cp16(sb + (FV(0) + f * 4) * 4, Vg + f * 4);
        }
        CP_COMMIT();
#pragma unroll
        for (int i = 0; i < 2; i++) {
            int f = tid + i * 256;
            cp16(sb + (FK(1) + f * 4) * 4, Kg + 2048 + f * 4);
            cp16(sb + (FV(1) + f * 4) * 4, Vg + 2048 + f * 4);
        }
        CP_COMMIT();

        CP_WAIT2();
        __syncthreads();

        uint32_t qf[4][4];
#pragma unroll
        for (int ks = 0; ks < 4; ks++) {
            uint4 av = *((const uint4*)(smu + FQ + (w * 4 + ks) * 128) + lane);
            qf[ks][0] = av.x; qf[ks][1] = av.y;
            qf[ks][2] = av.z; qf[ks][3] = av.w;
        }

        float m_i[2] = {-1e30f, -1e30f};
        float l_i[2] = {0.0f, 0.0f};
        float acc[8][4];
#pragma unroll
        for (int ni = 0; ni < 8; ni++)
#pragma unroll
            for (int cc = 0; cc < 4; cc++) acc[ni][cc] = 0.0f;

        for (int kb = 0; kb < nkt; kb++) {
            const int b = kb % 3;
            const uint32_t* Ks = smu + FK(b);
            const uint32_t* Vs = smu + FV(b);

            if (kb + 1 < nkt) { CP_WAIT1(); } else { CP_WAIT0(); }
            __syncthreads();

            if (kb + 2 < nkt) {
                const int b2 = (kb + 2) % 3;
                const uint32_t* Kn = Kg + (size_t)(kb + 2) * 2048;
                const uint32_t* Vn = Vg + (size_t)(kb + 2) * 2048;
#pragma unroll
                for (int i = 0; i < 2; i++) {
                    int f = tid + i * 256;
                    cp16(sb + (FK(b2) + f * 4) * 4, Kn + f * 4);
                    cp16(sb + (FV(b2) + f * 4) * 4, Vn + f * 4);
                }
                CP_COMMIT();
            }

            if (kb == 2 * qt + 1 && w < 4) continue;

            // ---- S = Q K^T ----
            float s[8][4];
#pragma unroll
            for (int ni = 0; ni < 8; ni++)
#pragma unroll
                for (int cc = 0; cc < 4; cc++) s[ni][cc] = 0.0f;

#pragma unroll
            for (int kp = 0; kp < 2; kp++) {
#pragma unroll
                for (int ni = 0; ni < 8; ni++) {
                    uint4 bv = *((const uint4*)(Ks + (ni * 2 + kp) * 128) + lane);
                    mma16(s[ni], qf[2 * kp],     bv.x, bv.y);
                    mma16(s[ni], qf[2 * kp + 1], bv.z, bv.w);
                }
            }

            // ---- scale + causal mask + online softmax (log2 domain) ----
            const int k0 = kb * 64;
            const bool mt = (kb >= 2 * qt);
            const int r0g = q0 + w * 16 + gid;
            float rmax[2] = {-1e30f, -1e30f};
#pragma unroll
            for (int ni = 0; ni < 8; ni++) {
                int colb = k0 + ni * 8 + 2 * sub;
#pragma unroll
                for (int cc = 0; cc < 4; cc++) {
                    float sv = s[ni][cc] * SCL;
                    if (mt) {
                        int row = r0g + ((cc >> 1) << 3);
                        int col = colb + (cc & 1);
                        if (col > row) sv = -1e30f;
                    }
                    s[ni][cc] = sv;
                    rmax[cc >> 1] = fmaxf(rmax[cc >> 1], sv);
                }
            }
#pragma unroll
            for (int o = 1; o <= 2; o <<= 1) {
                rmax[0] = fmaxf(rmax[0], __shfl_xor_sync(0xffffffffu, rmax[0], o));
                rmax[1] = fmaxf(rmax[1], __shfl_xor_sync(0xffffffffu, rmax[1], o));
            }
            float mnew0 = fmaxf(m_i[0], rmax[0]);
            float mnew1 = fmaxf(m_i[1], rmax[1]);
            float corr0 = exp2f(m_i[0] - mnew0);
            float corr1 = exp2f(m_i[1] - mnew1);
            m_i[0] = mnew0; m_i[1] = mnew1;

            // ---- p = 2^(s-m) via f16x2 MUFU; rsum from the rounded p ----
            uint32_t pa[4][4];
            float rsum[2] = {0.0f, 0.0f};
#pragma unroll
            for (int ni = 0; ni < 8; ni++) {
                uint32_t e0 = h2exp2(pk(s[ni][0] - mnew0, s[ni][1] - mnew0));
                uint32_t e1 = h2exp2(pk(s[ni][2] - mnew1, s[ni][3] - mnew1));
                pa[ni >> 1][(ni & 1) * 2]     = e0;
                pa[ni >> 1][(ni & 1) * 2 + 1] = e1;
                float2 f0 = h2f2(e0);
                float2 f1 = h2f2(e1);
                rsum[0] += f0.x + f0.y;
                rsum[1] += f1.x + f1.y;
                acc[ni][0] *= corr0; acc[ni][1] *= corr0;
                acc[ni][2] *= corr1; acc[ni][3] *= corr1;
            }
#pragma unroll
            for (int o = 1; o <= 2; o <<= 1) {
                rsum[0] += __shfl_xor_sync(0xffffffffu, rsum[0], o);
                rsum[1] += __shfl_xor_sync(0xffffffffu, rsum[1], o);
            }
            l_i[0] = l_i[0] * corr0 + rsum[0];
            l_i[1] = l_i[1] * corr1 + rsum[1];

            // ---- O += P V (V in B2) ----
#pragma unroll
            for (int jp = 0; jp < 2; jp++) {
#pragma unroll
                for (int ni = 0; ni < 8; ni++) {
                    uint4 bv = *((const uint4*)(Vs + (jp * 8 + ni) * 128) + lane);
                    mma16(acc[ni], pa[2 * jp],     bv.x, bv.y);
                    mma16(acc[ni], pa[2 * jp + 1], bv.z, bv.w);
                }
            }
        }

        {
            int m16 = bb * 128 + qt * 8 + w;
            float inv0 = 1.0f / l_i[0];
            float inv1 = 1.0f / l_i[1];
#pragma unroll
            for (int j = 0; j < 4; j++) {
                uint4 o = make_uint4(
                    pk(acc[2 * j][0] * inv0,     acc[2 * j][1] * inv0),
                    pk(acc[2 * j][2] * inv1,     acc[2 * j][3] * inv1),
                    pk(acc[2 * j + 1][0] * inv0, acc[2 * j + 1][1] * inv0),
                    pk(acc[2 * j + 1][2] * inv1, acc[2 * j + 1][3] * inv1));
                *(uint4*)(g_op + ((size_t)m16 * (Dd / 16) + h * 4 + j) * 128 + lane * 4) = o;
            }
        }
        __syncthreads();
    }
}

// ======================================================================
// Launch
// ======================================================================
extern "C" void kernel_launch(void* const* d_in, const int* in_sizes, int n_in,
                              void* d_out, int out_size)
{
    const float* x  = (const float*)d_in[0];
    const float* wq = (const float*)d_in[1];
    const float* wk = (const float*)d_in[2];
    const float* wv = (const float*)d_in[3];
    const float* wo = (const float*)d_in[4];
    float* out = (float*)d_out;

    cudaFuncSetAttribute(gemm_qkv, cudaFuncAttributeMaxDynamicSharedMemorySize, GEMM_SMEM);
    cudaFuncSetAttribute(gemm_o,   cudaFuncAttributeMaxDynamicSharedMemorySize, GEMM_SMEM);
    cudaFuncSetAttribute(flash_tc, cudaFuncAttributeMaxDynamicSharedMemorySize, FA_SMEM);

    // 0) ONE prep kernel: RoPE tables + all operand permutes
    prep<<<dim3(Mm / 64, Dd / 64, 2), 256>>>(x, wq, wk, wo, wv);

    // 1) fused q/k/v projections + RoPE + frag-permute epilogues
    gemm_qkv<<<dim3(Dd / 128, Mm / 128, 3), 128, GEMM_SMEM>>>();

    // 2) causal flash attention (8-warp CTAs, balanced paired q-tiles)
    flash_tc<<<dim3(NT / 2, Bb * Hh), 256, FA_SMEM>>>();

    // 3) output projection
    gemm_o<<<dim3(Dd / 128, Mm / 128), 128, GEMM_SMEM>>>(out);
}